// round 12
// baseline (speedup 1.0000x reference)
#include <cuda_runtime.h>
#include <cuda_bf16.h>
#include <cuda_fp16.h>
#include <math.h>
#include <stdint.h>

#define NB   8
#define NS   512
#define ND   1024
#define NH   16
#define NHD  64
#define S2   1024
#define BSq  4096
#define BT   8192
#define D3   3072
#define D4   4096

// weight layout inside g_wall (element offsets)
#define O_WQS 0u
#define O_WQA 3145728u
#define O_WAI 6291456u
#define O_WAO 9437184u
#define O_W1S 10485760u
#define O_W2S 14680064u
#define O_W1A 18874368u
#define O_W2A 23068672u
#define WALL_N 27262976u

// ---------------------------------------------------------------------------
// Scratch (device globals)
// ---------------------------------------------------------------------------
__device__ __nv_bfloat16 g_wall[WALL_N];
__device__ __nv_bfloat16 g_xsb [BSq * ND];
__device__ __nv_bfloat16 g_xab [BSq * ND];
__device__ __nv_bfloat16 g_qkvb[3 * BT * ND];     // roped q,k | v (token-major)
__device__ __half        g_hh  [3 * BT * ND];     // fp16 head-major q,k,v
__device__ __nv_bfloat16 g_ob  [BT * ND];
__device__ __nv_bfloat16 g_yb  [BT * ND];
__device__ __nv_bfloat16 g_h1b [2 * BSq * D4];

// ---------------------------------------------------------------------------
// PTX helpers (sm_80-era only)
// ---------------------------------------------------------------------------
__device__ __forceinline__ uint32_t smem_u32(const void* p) {
    uint32_t a;
    asm("{ .reg .u64 t; cvta.to.shared.u64 t, %1; cvt.u32.u64 %0, t; }"
        : "=r"(a) : "l"(p));
    return a;
}

__device__ __forceinline__ void cp16(uint32_t dst, const void* src) {
    asm volatile("cp.async.cg.shared.global [%0], [%1], 16;"
                 :: "r"(dst), "l"(src) : "memory");
}

__device__ __forceinline__ void ldm4(uint32_t addr, uint32_t* r) {
    asm volatile("ldmatrix.sync.aligned.m8n8.x4.shared.b16 {%0,%1,%2,%3}, [%4];"
                 : "=r"(r[0]), "=r"(r[1]), "=r"(r[2]), "=r"(r[3]) : "r"(addr));
}

__device__ __forceinline__ void ldm4t(uint32_t addr, uint32_t* r) {
    asm volatile("ldmatrix.sync.aligned.m8n8.x4.trans.shared.b16 {%0,%1,%2,%3}, [%4];"
                 : "=r"(r[0]), "=r"(r[1]), "=r"(r[2]), "=r"(r[3]) : "r"(addr));
}

__device__ __forceinline__ void mma16816(float* c, const uint32_t* a, const uint32_t* b) {
    asm volatile(
        "mma.sync.aligned.m16n8k16.row.col.f32.bf16.bf16.f32 "
        "{%0,%1,%2,%3}, {%4,%5,%6,%7}, {%8,%9}, {%0,%1,%2,%3};"
        : "+f"(c[0]), "+f"(c[1]), "+f"(c[2]), "+f"(c[3])
        : "r"(a[0]), "r"(a[1]), "r"(a[2]), "r"(a[3]), "r"(b[0]), "r"(b[1]));
}

__device__ __forceinline__ void mma16816h(float* c, const uint32_t* a, const uint32_t* b) {
    asm volatile(
        "mma.sync.aligned.m16n8k16.row.col.f32.f16.f16.f32 "
        "{%0,%1,%2,%3}, {%4,%5,%6,%7}, {%8,%9}, {%0,%1,%2,%3};"
        : "+f"(c[0]), "+f"(c[1]), "+f"(c[2]), "+f"(c[3])
        : "r"(a[0]), "r"(a[1]), "r"(a[2]), "r"(a[3]), "r"(b[0]), "r"(b[1]));
}

__device__ __forceinline__ uint32_t h2pack(float a, float b) {
    __half2 t = __floats2half2_rn(a, b);
    return *reinterpret_cast<uint32_t*>(&t);
}

// ---------------------------------------------------------------------------
// Prep kernel: weight fp32->bf16 conversion (blocks 0..26623) +
// modulation (blocks 26624..30719, vectorized x4)
// ---------------------------------------------------------------------------
struct PrepArgs {
    const float* src[8];
    const float* sz;
    const float* az;
    const float* e;
};

__global__ void prep_kernel(PrepArgs a) {
    int b = blockIdx.x;
    if (b < 26624) {
        const float* s;
        int base;
        if (b < 10240) {
            if (b < 6144) { if (b < 3072) { s = a.src[0]; base = 0; }
                            else          { s = a.src[1]; base = 3072; } }
            else          { if (b < 9216) { s = a.src[2]; base = 6144; }
                            else          { s = a.src[3]; base = 9216; } }
        } else {
            if (b < 18432) { if (b < 14336) { s = a.src[4]; base = 10240; }
                             else           { s = a.src[5]; base = 14336; } }
            else           { if (b < 22528) { s = a.src[6]; base = 18432; }
                             else           { s = a.src[7]; base = 22528; } }
        }
        int local = (b - base) * 1024 + threadIdx.x * 4;
        size_t g  = (size_t)b * 1024 + threadIdx.x * 4;
        float4 v = *(const float4*)(s + local);
        *(__nv_bfloat162*)(g_wall + g)     = __floats2bfloat162_rn(v.x, v.y);
        *(__nv_bfloat162*)(g_wall + g + 2) = __floats2bfloat162_rn(v.z, v.w);
    } else {
        int idx = (b - 26624) * 1024 + threadIdx.x * 4;   // 4 consecutive elements
        int bb = idx >> 19;
        int k  = idx & (ND - 1);
        const float* eb = a.e + bb * 3 * ND;
        float4 sh = *(const float4*)(eb + k);
        float4 sc = *(const float4*)(eb + ND + k);
        float4 zs = *(const float4*)(a.sz + idx);
        float4 za = *(const float4*)(a.az + idx);
        *(__nv_bfloat162*)(g_xsb + idx) =
            __floats2bfloat162_rn((1.0f + sc.x) * zs.x + sh.x, (1.0f + sc.y) * zs.y + sh.y);
        *(__nv_bfloat162*)(g_xsb + idx + 2) =
            __floats2bfloat162_rn((1.0f + sc.z) * zs.z + sh.z, (1.0f + sc.w) * zs.w + sh.w);
        *(__nv_bfloat162*)(g_xab + idx) =
            __floats2bfloat162_rn((1.0f + sc.x) * za.x + sh.x, (1.0f + sc.y) * za.y + sh.y);
        *(__nv_bfloat162*)(g_xab + idx + 2) =
            __floats2bfloat162_rn((1.0f + sc.z) * za.z + sh.z, (1.0f + sc.w) * za.w + sh.w);
    }
}

// ---------------------------------------------------------------------------
// bf16 GEMM via mma.sync — BK=64, 3-stage, 144B pitch, SINGLE sync per iter,
// NO register cap (the R6 regression came from __launch_bounds__(256,2)).
// MODE 0: merged QKV (branch halves, N=3072, K=1024) + FUSED ROPE -> bf16 g_qkvb
// MODE 1: merged headproj (thirds q/k/v, N=1024, K=1024, fp16 head-major)
// MODE 2: merged MLP1  (branch halves, N=4096, K=1024, gelu -> bf16, a_split)
// MODE 3: merged MLP2  (branch halves, N=1024, K=4096, residual fp32)
// MODE 4: out-proj     (N=1024, K=1024, bf16 out)
// ---------------------------------------------------------------------------
#define PITCH  144
#define STG64  (128 * PITCH)       // 18432 B per operand-stage
#define STAGES 3
#define DSMEM_BYTES (2 * STAGES * STG64)   // 110592

template<int MODE>
__global__ void __launch_bounds__(256) gemm_mma(
    const __nv_bfloat16* __restrict__ A0, const __nv_bfloat16* __restrict__ A1,
    const __nv_bfloat16* __restrict__ W0, const __nv_bfloat16* __restrict__ W1,
    const float* __restrict__ b0, const float* __restrict__ b1,
    void* __restrict__ C0, void* __restrict__ C1,
    const float* __restrict__ Z0, const float* __restrict__ Z1,
    const float* __restrict__ E)
{
    constexpr int N  = (MODE == 0) ? 3072 : (MODE == 2) ? 4096 : 1024;
    constexpr int K  = (MODE == 3) ? 4096 : 1024;
    constexpr int NK = K / 64;

    extern __shared__ char sm_[];
    const uint32_t Ab = smem_u32(sm_);
    const uint32_t Bb = Ab + STAGES * STG64;

    int tid = threadIdx.x, lane = tid & 31, wid = tid >> 5;
    int wm = wid & 1, wn = wid >> 1;
    int my = blockIdx.y;
    int bn = blockIdx.x * 128;

    const __nv_bfloat16* A;
    const __nv_bfloat16* W;
    const float* bias;
    const float* Z = nullptr;
    void* C = nullptr;
    int bm, branch = 0;

    if (MODE == 0) {
        branch = my >> 5;
        A = branch ? A1 : A0;  W = branch ? W1 : W0;
        bias = branch ? b1 : b0;
        bm = (my & 31) * 128;
    } else if (MODE == 1) {
        int third = my >> 6;
        A = A0 + (size_t)third * (BT * ND);
        W = W0 + (size_t)third * (ND * ND);
        bias = b0 + third * ND;
        C = (void*)((__half*)C0 + (size_t)third * (BT * ND));
        bm = (my & 63) * 128;
    } else if (MODE == 2) {
        branch = my >> 5;
        A = A0;  W = branch ? W1 : W0;  bias = branch ? b1 : b0;
        C = (void*)((__nv_bfloat16*)C0 + (size_t)branch * (BSq * D4));
        bm = (my & 31) * 128;
    } else if (MODE == 3) {
        branch = my >> 5;
        A = A0 + (size_t)branch * (BSq * D4);
        W = branch ? W1 : W0;  bias = branch ? b1 : b0;
        Z = branch ? Z1 : Z0;
        C = (void*)((float*)C0 + (size_t)branch * (BSq * ND));
        bm = (my & 31) * 128;
    } else {
        A = A0; W = W0; bias = b0; C = C0;
        bm = my * 128;
    }

    // --- global load geometry: 1 row per 2 threads; each thread 4x16B per operand
    int lr = tid >> 1, lc = tid & 1;
    int am = bm + lr;
    int arow = (MODE == 2) ? (((am >> 9) << 10) + branch * NS + (am & (NS - 1))) : am;
    const __nv_bfloat16* Ag = A + (size_t)arow * K + lc * 32;
    const __nv_bfloat16* Wg = W + (size_t)(bn + lr) * K + lc * 32;
    uint32_t dsto = (uint32_t)(lr * PITCH + lc * 64);

    // --- compute-side smem fragment offsets
    uint32_t aoff = (uint32_t)((wm * 64 + (lane & 15)) * PITCH + (lane >> 4) * 16);
    uint32_t boff = (uint32_t)((wn * 32 + (lane >> 4) * 8 + (lane & 7)) * PITCH
                               + ((lane >> 3) & 1) * 16);

    float acc[4][4][4] = {};

    // prologue: stages 0, 1
#pragma unroll
    for (int s = 0; s < STAGES - 1; s++) {
        uint32_t a = Ab + s * STG64, b = Bb + s * STG64;
        const __nv_bfloat16* ag = Ag + s * 64;
        const __nv_bfloat16* wg = Wg + s * 64;
#pragma unroll
        for (int i = 0; i < 4; i++) {
            cp16(a + dsto + i * 16, ag + i * 8);
            cp16(b + dsto + i * 16, wg + i * 8);
        }
        asm volatile("cp.async.commit_group;" ::: "memory");
    }

    for (int kt = 0; kt < NK; kt++) {
        asm volatile("cp.async.wait_group %0;" :: "n"(STAGES - 2) : "memory");
        __syncthreads();

        // prefetch stage kt+2 (safe under single barrier with 3 stages)
        int j = kt + STAGES - 1;
        if (j < NK) {
            int sj = j % STAGES;
            uint32_t a = Ab + sj * STG64, b = Bb + sj * STG64;
            const __nv_bfloat16* ag = Ag + (size_t)j * 64;
            const __nv_bfloat16* wg = Wg + (size_t)j * 64;
#pragma unroll
            for (int i = 0; i < 4; i++) {
                cp16(a + dsto + i * 16, ag + i * 8);
                cp16(b + dsto + i * 16, wg + i * 8);
            }
        }
        asm volatile("cp.async.commit_group;" ::: "memory");

        // compute on stage kt (4 k-slices of 16)
        int s = kt % STAGES;
        uint32_t a0 = Ab + s * STG64 + aoff;
        uint32_t b0s = Bb + s * STG64 + boff;
#pragma unroll
        for (int ks = 0; ks < 4; ks++) {
            uint32_t af[4][4], bf[2][4];
#pragma unroll
            for (int mf = 0; mf < 4; mf++) ldm4(a0 + mf * 16 * PITCH + ks * 32, af[mf]);
#pragma unroll
            for (int nn = 0; nn < 2; nn++) ldm4(b0s + nn * 16 * PITCH + ks * 32, bf[nn]);
#pragma unroll
            for (int mf = 0; mf < 4; mf++)
#pragma unroll
                for (int nf = 0; nf < 4; nf++)
                    mma16816(acc[mf][nf], af[mf], &bf[nf >> 1][(nf & 1) * 2]);
        }
    }

    // --- epilogue: fragments -> global, fused bias + transform
    int gr = lane >> 2, gc = (lane & 3) * 2;
#pragma unroll
    for (int mf = 0; mf < 4; mf++) {
#pragma unroll
        for (int nf = 0; nf < 4; nf++) {
            float* c = acc[mf][nf];
            int n  = bn + wn * 32 + nf * 8 + gc;
            int m0 = bm + wm * 64 + mf * 16 + gr;
            float bn0 = bias[n], bn1 = bias[n + 1];
            // MODE 0: rope frequency depends only on n
            float inv = 0.0f;
            if (MODE == 0) {
                inv = __expf(-6.238324625039508f * (float)(n & 1023) * (1.0f / 1024.0f));
            }
#pragma unroll
            for (int half = 0; half < 2; half++) {
                int m = m0 + half * 8;
                float v0 = c[half * 2]     + bn0;
                float v1 = c[half * 2 + 1] + bn1;
                if (MODE == 0) {
                    // fused RoPE + concat -> bf16 g_qkvb
                    int sec   = n >> 10;                // 0=q, 1=k, 2=v
                    int s_pos = m & (NS - 1);
                    int bb    = m >> 9;
                    size_t dst = ((size_t)(bb << 10) + (size_t)branch * NS + s_pos) * ND
                                 + (n & 1023);
                    if (sec < 2) {
                        float th = (float)s_pos * inv;
                        float sn, cs;
                        __sincosf(th, &sn, &cs);
                        float re = v0 * cs - v1 * sn;
                        float im = v0 * sn + v1 * cs;
                        __nv_bfloat16* base = g_qkvb + (size_t)sec * (BT * ND);
                        *(__nv_bfloat162*)(base + dst) = __floats2bfloat162_rn(re, im);
                    } else {
                        *(__nv_bfloat162*)(g_qkvb + 2 * (size_t)BT * ND + dst) =
                            __floats2bfloat162_rn(v0, v1);
                    }
                } else if (MODE == 1) {
                    int b = m >> 10, t = m & (S2 - 1), h = n >> 6;
                    __half* dst = (__half*)C + ((size_t)(b * NH + h) * S2 + t) * NHD + (n & 63);
                    *(__half2*)dst = __floats2half2_rn(v0, v1);
                } else if (MODE == 2) {
                    float x = v0;
                    float gx = 0.5f * x * (1.0f + tanhf(0.7978845608028654f * (x + 0.044715f * x * x * x)));
                    x = v1;
                    float gy = 0.5f * x * (1.0f + tanhf(0.7978845608028654f * (x + 0.044715f * x * x * x)));
                    *(__nv_bfloat162*)((__nv_bfloat16*)C + (size_t)m * N + n) =
                        __floats2bfloat162_rn(gx, gy);
                } else if (MODE == 3) {
                    int b = m >> 9;
                    const float* ep = E + (size_t)b * 3 * ND + 2 * ND + n;
                    const float* zp = Z + (size_t)m * N + n;
                    *(float2*)((float*)C + (size_t)m * N + n) =
                        make_float2(zp[0] + v0 * ep[0], zp[1] + v1 * ep[1]);
                } else {
                    *(__nv_bfloat162*)((__nv_bfloat16*)C + (size_t)m * N + n) =
                        __floats2bfloat162_rn(v0, v1);
                }
            }
        }
    }
}

// ---------------------------------------------------------------------------
// Flash attention via fp16 mma.sync. One block per (b, h, 128 q-rows).
// ---------------------------------------------------------------------------
#define AT_PITCH   144
#define AT_QBYTES  (128 * AT_PITCH)
#define AT_KVBYTES (64 * AT_PITCH)
#define AT_SMEM    (AT_QBYTES + 4 * AT_KVBYTES)

__global__ void __launch_bounds__(256) attn_mma_kernel()
{
    extern __shared__ char sm_[];
    uint32_t Qb = smem_u32(sm_);
    uint32_t Kb = Qb + AT_QBYTES;
    uint32_t Vb = Kb + 2 * AT_KVBYTES;

    int b = blockIdx.z, h = blockIdx.y, qt = blockIdx.x;
    int tid = threadIdx.x, lane = tid & 31, wid = tid >> 5;

    const __half* qg = g_hh + ((size_t)(b * NH + h) * S2 + qt * 128) * NHD;
    const __half* kg = g_hh + (size_t)BT * ND + (size_t)(b * NH + h) * S2 * NHD;
    const __half* vg = g_hh + 2 * (size_t)BT * ND + (size_t)(b * NH + h) * S2 * NHD;

    for (int i = tid; i < 1024; i += 256) {
        int row = i >> 3, c = i & 7;
        cp16(Qb + row * AT_PITCH + c * 16, qg + row * 64 + c * 8);
    }
    asm volatile("cp.async.commit_group;" ::: "memory");

    for (int i = tid; i < 512; i += 256) {
        int row = i >> 3, c = i & 7;
        cp16(Kb + row * AT_PITCH + c * 16, kg + row * 64 + c * 8);
        cp16(Vb + row * AT_PITCH + c * 16, vg + row * 64 + c * 8);
    }
    asm volatile("cp.async.commit_group;" ::: "memory");

    uint32_t q_off    = Qb + (wid * 16 + (lane & 15)) * AT_PITCH + (lane >> 4) * 16;
    uint32_t k_rowpat = (lane >> 4) * 8 + (lane & 7);
    uint32_t k_colpat = ((lane >> 3) & 1) * 16;
    uint32_t v_rowpat = lane & 15;
    uint32_t v_colpat = ((lane >> 4) & 1) * 16;

    float o[8][4] = {};
    float mrow0 = -1e30f, mrow1 = -1e30f;
    float lrow0 = 0.f, lrow1 = 0.f;

    for (int kt = 0; kt < 16; kt++) {
        if (kt + 1 < 16) {
            uint32_t kd = Kb + ((kt + 1) & 1) * AT_KVBYTES;
            uint32_t vd = Vb + ((kt + 1) & 1) * AT_KVBYTES;
            const __half* ks = kg + (size_t)(kt + 1) * 64 * 64;
            const __half* vs = vg + (size_t)(kt + 1) * 64 * 64;
            for (int i = tid; i < 512; i += 256) {
                int row = i >> 3, c = i & 7;
                cp16(kd + row * AT_PITCH + c * 16, ks + row * 64 + c * 8);
                cp16(vd + row * AT_PITCH + c * 16, vs + row * 64 + c * 8);
            }
        }
        asm volatile("cp.async.commit_group;" ::: "memory");
        asm volatile("cp.async.wait_group 1;" ::: "memory");
        __syncthreads();

        uint32_t ksm = Kb + (kt & 1) * AT_KVBYTES;
        uint32_t vsm = Vb + (kt & 1) * AT_KVBYTES;

        float s[8][4] = {};
#pragma unroll
        for (int kk = 0; kk < 4; kk++) {
            uint32_t qf[4];
            ldm4(q_off + kk * 32, qf);
#pragma unroll
            for (int nt = 0; nt < 4; nt++) {
                uint32_t kf[4];
                ldm4(ksm + (nt * 16 + k_rowpat) * AT_PITCH + k_colpat + kk * 32, kf);
                mma16816h(s[nt * 2],     qf, kf);
                mma16816h(s[nt * 2 + 1], qf, kf + 2);
            }
        }

        float mn0 = mrow0, mn1 = mrow1;
#pragma unroll
        for (int j = 0; j < 8; j++) {
            s[j][0] *= 0.125f; s[j][1] *= 0.125f; s[j][2] *= 0.125f; s[j][3] *= 0.125f;
            mn0 = fmaxf(mn0, fmaxf(s[j][0], s[j][1]));
            mn1 = fmaxf(mn1, fmaxf(s[j][2], s[j][3]));
        }
        mn0 = fmaxf(mn0, __shfl_xor_sync(0xffffffffu, mn0, 1));
        mn0 = fmaxf(mn0, __shfl_xor_sync(0xffffffffu, mn0, 2));
        mn1 = fmaxf(mn1, __shfl_xor_sync(0xffffffffu, mn1, 1));
        mn1 = fmaxf(mn1, __shfl_xor_sync(0xffffffffu, mn1, 2));
        float al0 = __expf(mrow0 - mn0), al1 = __expf(mrow1 - mn1);
        mrow0 = mn0; mrow1 = mn1;

        float ls0 = 0.f, ls1 = 0.f;
        uint32_t p[8][2];
#pragma unroll
        for (int j = 0; j < 8; j++) {
            float p0 = __expf(s[j][0] - mn0), p1 = __expf(s[j][1] - mn0);
            float p2 = __expf(s[j][2] - mn1), p3 = __expf(s[j][3] - mn1);
            ls0 += p0 + p1; ls1 += p2 + p3;
            p[j][0] = h2pack(p0, p1);
            p[j][1] = h2pack(p2, p3);
        }
        lrow0 = lrow0 * al0 + ls0;
        lrow1 = lrow1 * al1 + ls1;
#pragma unroll
        for (int j = 0; j < 8; j++) {
            o[j][0] *= al0; o[j][1] *= al0; o[j][2] *= al1; o[j][3] *= al1;
        }

#pragma unroll
        for (int kp = 0; kp < 4; kp++) {
            uint32_t af[4] = { p[2 * kp][0], p[2 * kp][1], p[2 * kp + 1][0], p[2 * kp + 1][1] };
#pragma unroll
            for (int nt = 0; nt < 4; nt++) {
                uint32_t vf[4];
                ldm4t(vsm + (kp * 16 + v_rowpat) * AT_PITCH + nt * 32 + v_colpat, vf);
                mma16816h(o[nt * 2],     af, vf);
                mma16816h(o[nt * 2 + 1], af, vf + 2);
            }
        }
        __syncthreads();
    }

    float lt0 = lrow0;
    lt0 += __shfl_xor_sync(0xffffffffu, lt0, 1);
    lt0 += __shfl_xor_sync(0xffffffffu, lt0, 2);
    float lt1 = lrow1;
    lt1 += __shfl_xor_sync(0xffffffffu, lt1, 1);
    lt1 += __shfl_xor_sync(0xffffffffu, lt1, 2);
    float inv0 = 1.0f / lt0, inv1 = 1.0f / lt1;

    int gr = lane >> 2, qc = (lane & 3) * 2;
    int r0 = qt * 128 + wid * 16 + gr;
    size_t base0 = ((size_t)b * S2 + r0) * ND + h * 64 + qc;
    size_t base1 = base0 + (size_t)8 * ND;
#pragma unroll
    for (int j = 0; j < 8; j++) {
        *(__nv_bfloat162*)&g_ob[base0 + j * 8] =
            __floats2bfloat162_rn(o[j][0] * inv0, o[j][1] * inv0);
        *(__nv_bfloat162*)&g_ob[base1 + j * 8] =
            __floats2bfloat162_rn(o[j][2] * inv1, o[j][3] * inv1);
    }
}

// ---------------------------------------------------------------------------
// Launch sequence
// ---------------------------------------------------------------------------
extern "C" void kernel_launch(void* const* d_in, const int* in_sizes, int n_in,
                              void* d_out, int out_size)
{
    const float* state_z    = (const float*)d_in[0];
    const float* action_z   = (const float*)d_in[1];
    const float* e          = (const float*)d_in[2];
    const float* qkv_s_w    = (const float*)d_in[3];
    const float* qkv_s_b    = (const float*)d_in[4];
    const float* qkv_a_w    = (const float*)d_in[5];
    const float* qkv_a_b    = (const float*)d_in[6];
    const float* attn_in_w  = (const float*)d_in[7];
    const float* attn_in_b  = (const float*)d_in[8];
    const float* attn_out_w = (const float*)d_in[9];
    const float* attn_out_b = (const float*)d_in[10];
    const float* mw1s       = (const float*)d_in[11];
    const float* mb1s       = (const float*)d_in[12];
    const float* mw2s       = (const float*)d_in[13];
    const float* mb2s       = (const float*)d_in[14];
    const float* mw1a       = (const float*)d_in[15];
    const float* mb1a       = (const float*)d_in[16];
    const float* mw2a       = (const float*)d_in[17];
    const float* mb2a       = (const float*)d_in[18];
    float* out = (float*)d_out;

    __nv_bfloat16 *wall, *xsb, *xab, *qkvb, *ob, *yb, *h1b;
    __half *hh;
    cudaGetSymbolAddress((void**)&wall, g_wall);
    cudaGetSymbolAddress((void**)&xsb,  g_xsb);
    cudaGetSymbolAddress((void**)&xab,  g_xab);
    cudaGetSymbolAddress((void**)&qkvb, g_qkvb);
    cudaGetSymbolAddress((void**)&hh,   g_hh);
    cudaGetSymbolAddress((void**)&ob,   g_ob);
    cudaGetSymbolAddress((void**)&yb,   g_yb);
    cudaGetSymbolAddress((void**)&h1b,  g_h1b);

    cudaFuncSetAttribute(gemm_mma<0>, cudaFuncAttributeMaxDynamicSharedMemorySize, DSMEM_BYTES);
    cudaFuncSetAttribute(gemm_mma<1>, cudaFuncAttributeMaxDynamicSharedMemorySize, DSMEM_BYTES);
    cudaFuncSetAttribute(gemm_mma<2>, cudaFuncAttributeMaxDynamicSharedMemorySize, DSMEM_BYTES);
    cudaFuncSetAttribute(gemm_mma<3>, cudaFuncAttributeMaxDynamicSharedMemorySize, DSMEM_BYTES);
    cudaFuncSetAttribute(gemm_mma<4>, cudaFuncAttributeMaxDynamicSharedMemorySize, DSMEM_BYTES);
    cudaFuncSetAttribute(attn_mma_kernel, cudaFuncAttributeMaxDynamicSharedMemorySize, AT_SMEM);

    // 1. prep: weight conversion + modulation (single kernel)
    PrepArgs pa;
    pa.src[0] = qkv_s_w;  pa.src[1] = qkv_a_w;  pa.src[2] = attn_in_w;
    pa.src[3] = attn_out_w; pa.src[4] = mw1s;   pa.src[5] = mw2s;
    pa.src[6] = mw1a;     pa.src[7] = mw2a;
    pa.sz = state_z; pa.az = action_z; pa.e = e;
    prep_kernel<<<30720, 256>>>(pa);

    // 2. merged QKV GEMM with fused RoPE+concat -> g_qkvb (bf16)
    dim3 gq(D3 / 128, 64);
    gemm_mma<0><<<gq, 256, DSMEM_BYTES>>>(xsb, xab, wall + O_WQS, wall + O_WQA,
                                          qkv_s_b, qkv_a_b, nullptr, nullptr,
                                          nullptr, nullptr, nullptr);

    // 3. merged head projections (thirds q,k,v) -> fp16 head-major g_hh
    dim3 gh(ND / 128, 192);
    gemm_mma<1><<<gh, 256, DSMEM_BYTES>>>(qkvb, nullptr, wall + O_WAI, nullptr,
                                          attn_in_b, nullptr, hh, nullptr,
                                          nullptr, nullptr, nullptr);

    // 4. attention
    dim3 ga(S2 / 128, NH, NB);
    attn_mma_kernel<<<ga, 256, AT_SMEM>>>();

    // 5. output projection -> bf16
    dim3 go(ND / 128, 64);
    gemm_mma<4><<<go, 256, DSMEM_BYTES>>>(ob, nullptr, wall + O_WAO, nullptr,
                                          attn_out_b, nullptr, yb, nullptr,
                                          nullptr, nullptr, nullptr);

    // 6. merged MLP1 (gelu) -> g_h1b (both branches)
    dim3 g1(D4 / 128, 64);
    gemm_mma<2><<<g1, 256, DSMEM_BYTES>>>(yb, nullptr, wall + O_W1S, wall + O_W1A,
                                          mb1s, mb1a, h1b, nullptr,
                                          nullptr, nullptr, nullptr);

    // 7. merged MLP2 (gated residual) -> out
    dim3 g2(ND / 128, 64);
    gemm_mma<3><<<g2, 256, DSMEM_BYTES>>>(h1b, nullptr, wall + O_W2S, wall + O_W2A,
                                          mb2s, mb2a, out, nullptr,
                                          state_z, action_z, e);
}

// round 13
// speedup vs baseline: 1.1891x; 1.1891x over previous
#include <cuda_runtime.h>
#include <cuda_bf16.h>
#include <cuda_fp16.h>
#include <math.h>
#include <stdint.h>

#define NB   8
#define NS   512
#define ND   1024
#define NH   16
#define NHD  64
#define S2   1024
#define BSq  4096
#define BT   8192
#define D3   3072
#define D4   4096

// weight layout inside g_wall (element offsets)
#define O_WQS 0u
#define O_WQA 3145728u
#define O_WAI 6291456u
#define O_WAO 9437184u
#define O_W1S 10485760u
#define O_W2S 14680064u
#define O_W1A 18874368u
#define O_W2A 23068672u
#define WALL_N 27262976u

// ---------------------------------------------------------------------------
// Scratch (device globals)
// ---------------------------------------------------------------------------
__device__ __nv_bfloat16 g_wall[WALL_N];
__device__ __nv_bfloat16 g_xsb [BSq * ND];
__device__ __nv_bfloat16 g_xab [BSq * ND];
__device__ __nv_bfloat16 g_qkvb[3 * BT * ND];     // roped q,k | v (token-major)
__device__ __half        g_hh  [3 * BT * ND];     // fp16 head-major q,k,v
__device__ __nv_bfloat16 g_ob  [BT * ND];
__device__ __nv_bfloat16 g_yb  [BT * ND];
__device__ __nv_bfloat16 g_h1b [2 * BSq * D4];

// ---------------------------------------------------------------------------
// PTX helpers (sm_80-era only)
// ---------------------------------------------------------------------------
__device__ __forceinline__ uint32_t smem_u32(const void* p) {
    uint32_t a;
    asm("{ .reg .u64 t; cvta.to.shared.u64 t, %1; cvt.u32.u64 %0, t; }"
        : "=r"(a) : "l"(p));
    return a;
}

__device__ __forceinline__ void cp16(uint32_t dst, const void* src) {
    asm volatile("cp.async.cg.shared.global [%0], [%1], 16;"
                 :: "r"(dst), "l"(src) : "memory");
}

__device__ __forceinline__ void ldm4(uint32_t addr, uint32_t* r) {
    asm volatile("ldmatrix.sync.aligned.m8n8.x4.shared.b16 {%0,%1,%2,%3}, [%4];"
                 : "=r"(r[0]), "=r"(r[1]), "=r"(r[2]), "=r"(r[3]) : "r"(addr));
}

__device__ __forceinline__ void ldm4t(uint32_t addr, uint32_t* r) {
    asm volatile("ldmatrix.sync.aligned.m8n8.x4.trans.shared.b16 {%0,%1,%2,%3}, [%4];"
                 : "=r"(r[0]), "=r"(r[1]), "=r"(r[2]), "=r"(r[3]) : "r"(addr));
}

__device__ __forceinline__ void mma16816(float* c, const uint32_t* a, const uint32_t* b) {
    asm volatile(
        "mma.sync.aligned.m16n8k16.row.col.f32.bf16.bf16.f32 "
        "{%0,%1,%2,%3}, {%4,%5,%6,%7}, {%8,%9}, {%0,%1,%2,%3};"
        : "+f"(c[0]), "+f"(c[1]), "+f"(c[2]), "+f"(c[3])
        : "r"(a[0]), "r"(a[1]), "r"(a[2]), "r"(a[3]), "r"(b[0]), "r"(b[1]));
}

__device__ __forceinline__ void mma16816h(float* c, const uint32_t* a, const uint32_t* b) {
    asm volatile(
        "mma.sync.aligned.m16n8k16.row.col.f32.f16.f16.f32 "
        "{%0,%1,%2,%3}, {%4,%5,%6,%7}, {%8,%9}, {%0,%1,%2,%3};"
        : "+f"(c[0]), "+f"(c[1]), "+f"(c[2]), "+f"(c[3])
        : "r"(a[0]), "r"(a[1]), "r"(a[2]), "r"(a[3]), "r"(b[0]), "r"(b[1]));
}

__device__ __forceinline__ uint32_t h2pack(float a, float b) {
    __half2 t = __floats2half2_rn(a, b);
    return *reinterpret_cast<uint32_t*>(&t);
}

// ---------------------------------------------------------------------------
// Prep kernel: weight fp32->bf16 conversion (blocks 0..26623) +
// modulation (blocks 26624..30719, vectorized x4)
// ---------------------------------------------------------------------------
struct PrepArgs {
    const float* src[8];
    const float* sz;
    const float* az;
    const float* e;
};

__global__ void prep_kernel(PrepArgs a) {
    int b = blockIdx.x;
    if (b < 26624) {
        const float* s;
        int base;
        if (b < 10240) {
            if (b < 6144) { if (b < 3072) { s = a.src[0]; base = 0; }
                            else          { s = a.src[1]; base = 3072; } }
            else          { if (b < 9216) { s = a.src[2]; base = 6144; }
                            else          { s = a.src[3]; base = 9216; } }
        } else {
            if (b < 18432) { if (b < 14336) { s = a.src[4]; base = 10240; }
                             else           { s = a.src[5]; base = 14336; } }
            else           { if (b < 22528) { s = a.src[6]; base = 18432; }
                             else           { s = a.src[7]; base = 22528; } }
        }
        int local = (b - base) * 1024 + threadIdx.x * 4;
        size_t g  = (size_t)b * 1024 + threadIdx.x * 4;
        float4 v = *(const float4*)(s + local);
        *(__nv_bfloat162*)(g_wall + g)     = __floats2bfloat162_rn(v.x, v.y);
        *(__nv_bfloat162*)(g_wall + g + 2) = __floats2bfloat162_rn(v.z, v.w);
    } else {
        int idx = (b - 26624) * 1024 + threadIdx.x * 4;   // 4 consecutive elements
        int bb = idx >> 19;
        int k  = idx & (ND - 1);
        const float* eb = a.e + bb * 3 * ND;
        float4 sh = *(const float4*)(eb + k);
        float4 sc = *(const float4*)(eb + ND + k);
        float4 zs = *(const float4*)(a.sz + idx);
        float4 za = *(const float4*)(a.az + idx);
        *(__nv_bfloat162*)(g_xsb + idx) =
            __floats2bfloat162_rn((1.0f + sc.x) * zs.x + sh.x, (1.0f + sc.y) * zs.y + sh.y);
        *(__nv_bfloat162*)(g_xsb + idx + 2) =
            __floats2bfloat162_rn((1.0f + sc.z) * zs.z + sh.z, (1.0f + sc.w) * zs.w + sh.w);
        *(__nv_bfloat162*)(g_xab + idx) =
            __floats2bfloat162_rn((1.0f + sc.x) * za.x + sh.x, (1.0f + sc.y) * za.y + sh.y);
        *(__nv_bfloat162*)(g_xab + idx + 2) =
            __floats2bfloat162_rn((1.0f + sc.z) * za.z + sh.z, (1.0f + sc.w) * za.w + sh.w);
    }
}

// ---------------------------------------------------------------------------
// bf16 GEMM via mma.sync — BK=32, 4-STAGE cp.async, 80B pitch, single sync
// per iter (CUTLASS multistage order: wait -> sync -> prefetch+commit -> compute).
// MODE 0: merged QKV (branch halves, N=3072, K=1024) + FUSED ROPE -> bf16 g_qkvb
// MODE 1: merged headproj (thirds q/k/v, N=1024, K=1024, fp16 head-major)
// MODE 2: merged MLP1  (branch halves, N=4096, K=1024, gelu -> bf16, a_split)
// MODE 3: merged MLP2  (branch halves, N=1024, K=4096, residual fp32)
// MODE 4: out-proj     (N=1024, K=1024, bf16 out)
// ---------------------------------------------------------------------------
#define ROWB   80
#define STG    (128 * ROWB)        // 10240 B per operand-stage
#define STAGES 4
#define DSMEM_BYTES (2 * STAGES * STG)   // 81920

template<int MODE>
__global__ void __launch_bounds__(256) gemm_mma(
    const __nv_bfloat16* __restrict__ A0, const __nv_bfloat16* __restrict__ A1,
    const __nv_bfloat16* __restrict__ W0, const __nv_bfloat16* __restrict__ W1,
    const float* __restrict__ b0, const float* __restrict__ b1,
    void* __restrict__ C0, void* __restrict__ C1,
    const float* __restrict__ Z0, const float* __restrict__ Z1,
    const float* __restrict__ E)
{
    constexpr int N  = (MODE == 0) ? 3072 : (MODE == 2) ? 4096 : 1024;
    constexpr int K  = (MODE == 3) ? 4096 : 1024;
    constexpr int NK = K / 32;

    extern __shared__ char sm_[];
    const uint32_t Ab = smem_u32(sm_);
    const uint32_t Bb = Ab + STAGES * STG;

    int tid = threadIdx.x, lane = tid & 31, wid = tid >> 5;
    int wm = wid & 1, wn = wid >> 1;
    int my = blockIdx.y;
    int bn = blockIdx.x * 128;

    const __nv_bfloat16* A;
    const __nv_bfloat16* W;
    const float* bias;
    const float* Z = nullptr;
    void* C = nullptr;
    int bm, branch = 0;

    if (MODE == 0) {
        branch = my >> 5;
        A = branch ? A1 : A0;  W = branch ? W1 : W0;
        bias = branch ? b1 : b0;
        bm = (my & 31) * 128;
    } else if (MODE == 1) {
        int third = my >> 6;
        A = A0 + (size_t)third * (BT * ND);
        W = W0 + (size_t)third * (ND * ND);
        bias = b0 + third * ND;
        C = (void*)((__half*)C0 + (size_t)third * (BT * ND));
        bm = (my & 63) * 128;
    } else if (MODE == 2) {
        branch = my >> 5;
        A = A0;  W = branch ? W1 : W0;  bias = branch ? b1 : b0;
        C = (void*)((__nv_bfloat16*)C0 + (size_t)branch * (BSq * D4));
        bm = (my & 31) * 128;
    } else if (MODE == 3) {
        branch = my >> 5;
        A = A0 + (size_t)branch * (BSq * D4);
        W = branch ? W1 : W0;  bias = branch ? b1 : b0;
        Z = branch ? Z1 : Z0;
        C = (void*)((float*)C0 + (size_t)branch * (BSq * ND));
        bm = (my & 31) * 128;
    } else {
        A = A0; W = W0; bias = b0; C = C0;
        bm = my * 128;
    }

    // --- global load geometry: each thread 16B x (2 rows A + 2 rows B) per stage
    int lr = tid >> 2, lc = tid & 3;
    int am0 = bm + lr, am1 = bm + lr + 64;
    int ar0 = (MODE == 2) ? (((am0 >> 9) << 10) + branch * NS + (am0 & (NS - 1))) : am0;
    int ar1 = (MODE == 2) ? (((am1 >> 9) << 10) + branch * NS + (am1 & (NS - 1))) : am1;
    const __nv_bfloat16* Ag0 = A + (size_t)ar0 * K + lc * 8;
    const __nv_bfloat16* Ag1 = A + (size_t)ar1 * K + lc * 8;
    const __nv_bfloat16* Wg0 = W + (size_t)(bn + lr) * K + lc * 8;
    const __nv_bfloat16* Wg1 = W + (size_t)(bn + lr + 64) * K + lc * 8;
    uint32_t dst0 = (uint32_t)(lr * ROWB + lc * 16);
    uint32_t dst1 = dst0 + 64 * ROWB;

    // --- compute-side smem fragment offsets
    uint32_t aoff = (uint32_t)((wm * 64 + (lane & 15)) * ROWB + (lane >> 4) * 16);
    uint32_t boff = (uint32_t)((wn * 32 + (lane >> 4) * 8 + (lane & 7)) * ROWB
                               + ((lane >> 3) & 1) * 16);

    float acc[4][4][4] = {};

    // prologue: stages 0..STAGES-2
#pragma unroll
    for (int s = 0; s < STAGES - 1; s++) {
        uint32_t a = Ab + s * STG, b = Bb + s * STG;
        int ke = s * 32;
        cp16(a + dst0, Ag0 + ke); cp16(a + dst1, Ag1 + ke);
        cp16(b + dst0, Wg0 + ke); cp16(b + dst1, Wg1 + ke);
        asm volatile("cp.async.commit_group;" ::: "memory");
    }

    for (int kt = 0; kt < NK; kt++) {
        asm volatile("cp.async.wait_group %0;" :: "n"(STAGES - 2) : "memory");
        __syncthreads();

        // prefetch stage kt+STAGES-1 (safe: barrier above guarantees all warps
        // finished consuming stage (kt+STAGES-1)%STAGES == (kt-1)%STAGES)
        int j = kt + STAGES - 1;
        if (j < NK) {
            int sj = j % STAGES;
            uint32_t a = Ab + sj * STG, b = Bb + sj * STG;
            int ke = j * 32;
            cp16(a + dst0, Ag0 + ke); cp16(a + dst1, Ag1 + ke);
            cp16(b + dst0, Wg0 + ke); cp16(b + dst1, Wg1 + ke);
        }
        asm volatile("cp.async.commit_group;" ::: "memory");

        // compute on stage kt
        int s = kt % STAGES;
        uint32_t a0 = Ab + s * STG + aoff;
        uint32_t b0s = Bb + s * STG + boff;
#pragma unroll
        for (int ks = 0; ks < 2; ks++) {
            uint32_t af[4][4], bf[2][4];
#pragma unroll
            for (int mf = 0; mf < 4; mf++) ldm4(a0 + mf * 16 * ROWB + ks * 32, af[mf]);
#pragma unroll
            for (int nn = 0; nn < 2; nn++) ldm4(b0s + nn * 16 * ROWB + ks * 32, bf[nn]);
#pragma unroll
            for (int mf = 0; mf < 4; mf++)
#pragma unroll
                for (int nf = 0; nf < 4; nf++)
                    mma16816(acc[mf][nf], af[mf], &bf[nf >> 1][(nf & 1) * 2]);
        }
    }

    // --- epilogue: fragments -> global, fused bias + transform
    int gr = lane >> 2, gc = (lane & 3) * 2;
#pragma unroll
    for (int mf = 0; mf < 4; mf++) {
#pragma unroll
        for (int nf = 0; nf < 4; nf++) {
            float* c = acc[mf][nf];
            int n  = bn + wn * 32 + nf * 8 + gc;
            int m0 = bm + wm * 64 + mf * 16 + gr;
            float bn0 = bias[n], bn1 = bias[n + 1];
            // MODE 0: rope frequency depends only on n
            float inv = 0.0f;
            if (MODE == 0) {
                inv = __expf(-6.238324625039508f * (float)(n & 1023) * (1.0f / 1024.0f));
            }
#pragma unroll
            for (int half = 0; half < 2; half++) {
                int m = m0 + half * 8;
                float v0 = c[half * 2]     + bn0;
                float v1 = c[half * 2 + 1] + bn1;
                if (MODE == 0) {
                    // fused RoPE + concat -> bf16 g_qkvb
                    int sec   = n >> 10;                // 0=q, 1=k, 2=v
                    int s_pos = m & (NS - 1);
                    int bb    = m >> 9;
                    size_t dst = ((size_t)(bb << 10) + (size_t)branch * NS + s_pos) * ND
                                 + (n & 1023);
                    if (sec < 2) {
                        float th = (float)s_pos * inv;
                        float sn, cs;
                        __sincosf(th, &sn, &cs);
                        float re = v0 * cs - v1 * sn;
                        float im = v0 * sn + v1 * cs;
                        __nv_bfloat16* base = g_qkvb + (size_t)sec * (BT * ND);
                        *(__nv_bfloat162*)(base + dst) = __floats2bfloat162_rn(re, im);
                    } else {
                        *(__nv_bfloat162*)(g_qkvb + 2 * (size_t)BT * ND + dst) =
                            __floats2bfloat162_rn(v0, v1);
                    }
                } else if (MODE == 1) {
                    int b = m >> 10, t = m & (S2 - 1), h = n >> 6;
                    __half* dst = (__half*)C + ((size_t)(b * NH + h) * S2 + t) * NHD + (n & 63);
                    *(__half2*)dst = __floats2half2_rn(v0, v1);
                } else if (MODE == 2) {
                    float x = v0;
                    float gx = 0.5f * x * (1.0f + tanhf(0.7978845608028654f * (x + 0.044715f * x * x * x)));
                    x = v1;
                    float gy = 0.5f * x * (1.0f + tanhf(0.7978845608028654f * (x + 0.044715f * x * x * x)));
                    *(__nv_bfloat162*)((__nv_bfloat16*)C + (size_t)m * N + n) =
                        __floats2bfloat162_rn(gx, gy);
                } else if (MODE == 3) {
                    int b = m >> 9;
                    const float* ep = E + (size_t)b * 3 * ND + 2 * ND + n;
                    const float* zp = Z + (size_t)m * N + n;
                    *(float2*)((float*)C + (size_t)m * N + n) =
                        make_float2(zp[0] + v0 * ep[0], zp[1] + v1 * ep[1]);
                } else {
                    *(__nv_bfloat162*)((__nv_bfloat16*)C + (size_t)m * N + n) =
                        __floats2bfloat162_rn(v0, v1);
                }
            }
        }
    }
}

// ---------------------------------------------------------------------------
// Flash attention via fp16 mma.sync. One block per (b, h, 128 q-rows).
// ---------------------------------------------------------------------------
#define AT_PITCH   144
#define AT_QBYTES  (128 * AT_PITCH)
#define AT_KVBYTES (64 * AT_PITCH)
#define AT_SMEM    (AT_QBYTES + 4 * AT_KVBYTES)

__global__ void __launch_bounds__(256) attn_mma_kernel()
{
    extern __shared__ char sm_[];
    uint32_t Qb = smem_u32(sm_);
    uint32_t Kb = Qb + AT_QBYTES;
    uint32_t Vb = Kb + 2 * AT_KVBYTES;

    int b = blockIdx.z, h = blockIdx.y, qt = blockIdx.x;
    int tid = threadIdx.x, lane = tid & 31, wid = tid >> 5;

    const __half* qg = g_hh + ((size_t)(b * NH + h) * S2 + qt * 128) * NHD;
    const __half* kg = g_hh + (size_t)BT * ND + (size_t)(b * NH + h) * S2 * NHD;
    const __half* vg = g_hh + 2 * (size_t)BT * ND + (size_t)(b * NH + h) * S2 * NHD;

    for (int i = tid; i < 1024; i += 256) {
        int row = i >> 3, c = i & 7;
        cp16(Qb + row * AT_PITCH + c * 16, qg + row * 64 + c * 8);
    }
    asm volatile("cp.async.commit_group;" ::: "memory");

    for (int i = tid; i < 512; i += 256) {
        int row = i >> 3, c = i & 7;
        cp16(Kb + row * AT_PITCH + c * 16, kg + row * 64 + c * 8);
        cp16(Vb + row * AT_PITCH + c * 16, vg + row * 64 + c * 8);
    }
    asm volatile("cp.async.commit_group;" ::: "memory");

    uint32_t q_off    = Qb + (wid * 16 + (lane & 15)) * AT_PITCH + (lane >> 4) * 16;
    uint32_t k_rowpat = (lane >> 4) * 8 + (lane & 7);
    uint32_t k_colpat = ((lane >> 3) & 1) * 16;
    uint32_t v_rowpat = lane & 15;
    uint32_t v_colpat = ((lane >> 4) & 1) * 16;

    float o[8][4] = {};
    float mrow0 = -1e30f, mrow1 = -1e30f;
    float lrow0 = 0.f, lrow1 = 0.f;

    for (int kt = 0; kt < 16; kt++) {
        if (kt + 1 < 16) {
            uint32_t kd = Kb + ((kt + 1) & 1) * AT_KVBYTES;
            uint32_t vd = Vb + ((kt + 1) & 1) * AT_KVBYTES;
            const __half* ks = kg + (size_t)(kt + 1) * 64 * 64;
            const __half* vs = vg + (size_t)(kt + 1) * 64 * 64;
            for (int i = tid; i < 512; i += 256) {
                int row = i >> 3, c = i & 7;
                cp16(kd + row * AT_PITCH + c * 16, ks + row * 64 + c * 8);
                cp16(vd + row * AT_PITCH + c * 16, vs + row * 64 + c * 8);
            }
        }
        asm volatile("cp.async.commit_group;" ::: "memory");
        asm volatile("cp.async.wait_group 1;" ::: "memory");
        __syncthreads();

        uint32_t ksm = Kb + (kt & 1) * AT_KVBYTES;
        uint32_t vsm = Vb + (kt & 1) * AT_KVBYTES;

        float s[8][4] = {};
#pragma unroll
        for (int kk = 0; kk < 4; kk++) {
            uint32_t qf[4];
            ldm4(q_off + kk * 32, qf);
#pragma unroll
            for (int nt = 0; nt < 4; nt++) {
                uint32_t kf[4];
                ldm4(ksm + (nt * 16 + k_rowpat) * AT_PITCH + k_colpat + kk * 32, kf);
                mma16816h(s[nt * 2],     qf, kf);
                mma16816h(s[nt * 2 + 1], qf, kf + 2);
            }
        }

        float mn0 = mrow0, mn1 = mrow1;
#pragma unroll
        for (int j = 0; j < 8; j++) {
            s[j][0] *= 0.125f; s[j][1] *= 0.125f; s[j][2] *= 0.125f; s[j][3] *= 0.125f;
            mn0 = fmaxf(mn0, fmaxf(s[j][0], s[j][1]));
            mn1 = fmaxf(mn1, fmaxf(s[j][2], s[j][3]));
        }
        mn0 = fmaxf(mn0, __shfl_xor_sync(0xffffffffu, mn0, 1));
        mn0 = fmaxf(mn0, __shfl_xor_sync(0xffffffffu, mn0, 2));
        mn1 = fmaxf(mn1, __shfl_xor_sync(0xffffffffu, mn1, 1));
        mn1 = fmaxf(mn1, __shfl_xor_sync(0xffffffffu, mn1, 2));
        float al0 = __expf(mrow0 - mn0), al1 = __expf(mrow1 - mn1);
        mrow0 = mn0; mrow1 = mn1;

        float ls0 = 0.f, ls1 = 0.f;
        uint32_t p[8][2];
#pragma unroll
        for (int j = 0; j < 8; j++) {
            float p0 = __expf(s[j][0] - mn0), p1 = __expf(s[j][1] - mn0);
            float p2 = __expf(s[j][2] - mn1), p3 = __expf(s[j][3] - mn1);
            ls0 += p0 + p1; ls1 += p2 + p3;
            p[j][0] = h2pack(p0, p1);
            p[j][1] = h2pack(p2, p3);
        }
        lrow0 = lrow0 * al0 + ls0;
        lrow1 = lrow1 * al1 + ls1;
#pragma unroll
        for (int j = 0; j < 8; j++) {
            o[j][0] *= al0; o[j][1] *= al0; o[j][2] *= al1; o[j][3] *= al1;
        }

#pragma unroll
        for (int kp = 0; kp < 4; kp++) {
            uint32_t af[4] = { p[2 * kp][0], p[2 * kp][1], p[2 * kp + 1][0], p[2 * kp + 1][1] };
#pragma unroll
            for (int nt = 0; nt < 4; nt++) {
                uint32_t vf[4];
                ldm4t(vsm + (kp * 16 + v_rowpat) * AT_PITCH + nt * 32 + v_colpat, vf);
                mma16816h(o[nt * 2],     af, vf);
                mma16816h(o[nt * 2 + 1], af, vf + 2);
            }
        }
        __syncthreads();
    }

    float lt0 = lrow0;
    lt0 += __shfl_xor_sync(0xffffffffu, lt0, 1);
    lt0 += __shfl_xor_sync(0xffffffffu, lt0, 2);
    float lt1 = lrow1;
    lt1 += __shfl_xor_sync(0xffffffffu, lt1, 1);
    lt1 += __shfl_xor_sync(0xffffffffu, lt1, 2);
    float inv0 = 1.0f / lt0, inv1 = 1.0f / lt1;

    int gr = lane >> 2, qc = (lane & 3) * 2;
    int r0 = qt * 128 + wid * 16 + gr;
    size_t base0 = ((size_t)b * S2 + r0) * ND + h * 64 + qc;
    size_t base1 = base0 + (size_t)8 * ND;
#pragma unroll
    for (int j = 0; j < 8; j++) {
        *(__nv_bfloat162*)&g_ob[base0 + j * 8] =
            __floats2bfloat162_rn(o[j][0] * inv0, o[j][1] * inv0);
        *(__nv_bfloat162*)&g_ob[base1 + j * 8] =
            __floats2bfloat162_rn(o[j][2] * inv1, o[j][3] * inv1);
    }
}

// ---------------------------------------------------------------------------
// Launch sequence
// ---------------------------------------------------------------------------
extern "C" void kernel_launch(void* const* d_in, const int* in_sizes, int n_in,
                              void* d_out, int out_size)
{
    const float* state_z    = (const float*)d_in[0];
    const float* action_z   = (const float*)d_in[1];
    const float* e          = (const float*)d_in[2];
    const float* qkv_s_w    = (const float*)d_in[3];
    const float* qkv_s_b    = (const float*)d_in[4];
    const float* qkv_a_w    = (const float*)d_in[5];
    const float* qkv_a_b    = (const float*)d_in[6];
    const float* attn_in_w  = (const float*)d_in[7];
    const float* attn_in_b  = (const float*)d_in[8];
    const float* attn_out_w = (const float*)d_in[9];
    const float* attn_out_b = (const float*)d_in[10];
    const float* mw1s       = (const float*)d_in[11];
    const float* mb1s       = (const float*)d_in[12];
    const float* mw2s       = (const float*)d_in[13];
    const float* mb2s       = (const float*)d_in[14];
    const float* mw1a       = (const float*)d_in[15];
    const float* mb1a       = (const float*)d_in[16];
    const float* mw2a       = (const float*)d_in[17];
    const float* mb2a       = (const float*)d_in[18];
    float* out = (float*)d_out;

    __nv_bfloat16 *wall, *xsb, *xab, *qkvb, *ob, *yb, *h1b;
    __half *hh;
    cudaGetSymbolAddress((void**)&wall, g_wall);
    cudaGetSymbolAddress((void**)&xsb,  g_xsb);
    cudaGetSymbolAddress((void**)&xab,  g_xab);
    cudaGetSymbolAddress((void**)&qkvb, g_qkvb);
    cudaGetSymbolAddress((void**)&hh,   g_hh);
    cudaGetSymbolAddress((void**)&ob,   g_ob);
    cudaGetSymbolAddress((void**)&yb,   g_yb);
    cudaGetSymbolAddress((void**)&h1b,  g_h1b);

    cudaFuncSetAttribute(gemm_mma<0>, cudaFuncAttributeMaxDynamicSharedMemorySize, DSMEM_BYTES);
    cudaFuncSetAttribute(gemm_mma<1>, cudaFuncAttributeMaxDynamicSharedMemorySize, DSMEM_BYTES);
    cudaFuncSetAttribute(gemm_mma<2>, cudaFuncAttributeMaxDynamicSharedMemorySize, DSMEM_BYTES);
    cudaFuncSetAttribute(gemm_mma<3>, cudaFuncAttributeMaxDynamicSharedMemorySize, DSMEM_BYTES);
    cudaFuncSetAttribute(gemm_mma<4>, cudaFuncAttributeMaxDynamicSharedMemorySize, DSMEM_BYTES);
    cudaFuncSetAttribute(attn_mma_kernel, cudaFuncAttributeMaxDynamicSharedMemorySize, AT_SMEM);

    // 1. prep: weight conversion + modulation (single kernel)
    PrepArgs pa;
    pa.src[0] = qkv_s_w;  pa.src[1] = qkv_a_w;  pa.src[2] = attn_in_w;
    pa.src[3] = attn_out_w; pa.src[4] = mw1s;   pa.src[5] = mw2s;
    pa.src[6] = mw1a;     pa.src[7] = mw2a;
    pa.sz = state_z; pa.az = action_z; pa.e = e;
    prep_kernel<<<30720, 256>>>(pa);

    // 2. merged QKV GEMM with fused RoPE+concat -> g_qkvb (bf16)
    dim3 gq(D3 / 128, 64);
    gemm_mma<0><<<gq, 256, DSMEM_BYTES>>>(xsb, xab, wall + O_WQS, wall + O_WQA,
                                          qkv_s_b, qkv_a_b, nullptr, nullptr,
                                          nullptr, nullptr, nullptr);

    // 3. merged head projections (thirds q,k,v) -> fp16 head-major g_hh
    dim3 gh(ND / 128, 192);
    gemm_mma<1><<<gh, 256, DSMEM_BYTES>>>(qkvb, nullptr, wall + O_WAI, nullptr,
                                          attn_in_b, nullptr, hh, nullptr,
                                          nullptr, nullptr, nullptr);

    // 4. attention
    dim3 ga(S2 / 128, NH, NB);
    attn_mma_kernel<<<ga, 256, AT_SMEM>>>();

    // 5. output projection -> bf16
    dim3 go(ND / 128, 64);
    gemm_mma<4><<<go, 256, DSMEM_BYTES>>>(ob, nullptr, wall + O_WAO, nullptr,
                                          attn_out_b, nullptr, yb, nullptr,
                                          nullptr, nullptr, nullptr);

    // 6. merged MLP1 (gelu) -> g_h1b (both branches)
    dim3 g1(D4 / 128, 64);
    gemm_mma<2><<<g1, 256, DSMEM_BYTES>>>(yb, nullptr, wall + O_W1S, wall + O_W1A,
                                          mb1s, mb1a, h1b, nullptr,
                                          nullptr, nullptr, nullptr);

    // 7. merged MLP2 (gated residual) -> out
    dim3 g2(ND / 128, 64);
    gemm_mma<3><<<g2, 256, DSMEM_BYTES>>>(h1b, nullptr, wall + O_W2S, wall + O_W2A,
                                          mb2s, mb2a, out, nullptr,
                                          state_z, action_z, e);
}

// round 14
// speedup vs baseline: 1.1895x; 1.0003x over previous
#include <cuda_runtime.h>
#include <cuda_bf16.h>
#include <cuda_fp16.h>
#include <math.h>
#include <stdint.h>

#define NB   8
#define NS   512
#define ND   1024
#define NH   16
#define NHD  64
#define S2   1024
#define BSq  4096
#define BT   8192
#define D3   3072
#define D4   4096

// weight layout inside g_wall (element offsets)
#define O_WQS 0u
#define O_WQA 3145728u
#define O_WAI 6291456u
#define O_WAO 9437184u
#define O_W1S 10485760u
#define O_W2S 14680064u
#define O_W1A 18874368u
#define O_W2A 23068672u
#define WALL_N 27262976u

// ---------------------------------------------------------------------------
// Scratch (device globals)
// ---------------------------------------------------------------------------
__device__ __nv_bfloat16 g_wall[WALL_N];
__device__ __nv_bfloat16 g_xsb [BSq * ND];
__device__ __nv_bfloat16 g_xab [BSq * ND];
__device__ __nv_bfloat16 g_qkvb[3 * BT * ND];     // roped q,k | v (token-major)
__device__ __half        g_hh  [3 * BT * ND];     // fp16 head-major q,k,v (q pre-scaled)
__device__ __nv_bfloat16 g_ob  [BT * ND];
__device__ __nv_bfloat16 g_yb  [BT * ND];
__device__ __nv_bfloat16 g_h1b [2 * BSq * D4];

// ---------------------------------------------------------------------------
// PTX helpers (sm_80-era only)
// ---------------------------------------------------------------------------
__device__ __forceinline__ uint32_t smem_u32(const void* p) {
    uint32_t a;
    asm("{ .reg .u64 t; cvta.to.shared.u64 t, %1; cvt.u32.u64 %0, t; }"
        : "=r"(a) : "l"(p));
    return a;
}

__device__ __forceinline__ void cp16(uint32_t dst, const void* src) {
    asm volatile("cp.async.cg.shared.global [%0], [%1], 16;"
                 :: "r"(dst), "l"(src) : "memory");
}

__device__ __forceinline__ void ldm4(uint32_t addr, uint32_t* r) {
    asm volatile("ldmatrix.sync.aligned.m8n8.x4.shared.b16 {%0,%1,%2,%3}, [%4];"
                 : "=r"(r[0]), "=r"(r[1]), "=r"(r[2]), "=r"(r[3]) : "r"(addr));
}

__device__ __forceinline__ void ldm4t(uint32_t addr, uint32_t* r) {
    asm volatile("ldmatrix.sync.aligned.m8n8.x4.trans.shared.b16 {%0,%1,%2,%3}, [%4];"
                 : "=r"(r[0]), "=r"(r[1]), "=r"(r[2]), "=r"(r[3]) : "r"(addr));
}

__device__ __forceinline__ void mma16816(float* c, const uint32_t* a, const uint32_t* b) {
    asm volatile(
        "mma.sync.aligned.m16n8k16.row.col.f32.bf16.bf16.f32 "
        "{%0,%1,%2,%3}, {%4,%5,%6,%7}, {%8,%9}, {%0,%1,%2,%3};"
        : "+f"(c[0]), "+f"(c[1]), "+f"(c[2]), "+f"(c[3])
        : "r"(a[0]), "r"(a[1]), "r"(a[2]), "r"(a[3]), "r"(b[0]), "r"(b[1]));
}

__device__ __forceinline__ void mma16816h(float* c, const uint32_t* a, const uint32_t* b) {
    asm volatile(
        "mma.sync.aligned.m16n8k16.row.col.f32.f16.f16.f32 "
        "{%0,%1,%2,%3}, {%4,%5,%6,%7}, {%8,%9}, {%0,%1,%2,%3};"
        : "+f"(c[0]), "+f"(c[1]), "+f"(c[2]), "+f"(c[3])
        : "r"(a[0]), "r"(a[1]), "r"(a[2]), "r"(a[3]), "r"(b[0]), "r"(b[1]));
}

__device__ __forceinline__ uint32_t h2pack(float a, float b) {
    __half2 t = __floats2half2_rn(a, b);
    return *reinterpret_cast<uint32_t*>(&t);
}

// ---------------------------------------------------------------------------
// Prep kernel: weight fp32->bf16 conversion (blocks 0..26623) +
// modulation (blocks 26624..30719, vectorized x4)
// ---------------------------------------------------------------------------
struct PrepArgs {
    const float* src[8];
    const float* sz;
    const float* az;
    const float* e;
};

__global__ void prep_kernel(PrepArgs a) {
    int b = blockIdx.x;
    if (b < 26624) {
        const float* s;
        int base;
        if (b < 10240) {
            if (b < 6144) { if (b < 3072) { s = a.src[0]; base = 0; }
                            else          { s = a.src[1]; base = 3072; } }
            else          { if (b < 9216) { s = a.src[2]; base = 6144; }
                            else          { s = a.src[3]; base = 9216; } }
        } else {
            if (b < 18432) { if (b < 14336) { s = a.src[4]; base = 10240; }
                             else           { s = a.src[5]; base = 14336; } }
            else           { if (b < 22528) { s = a.src[6]; base = 18432; }
                             else           { s = a.src[7]; base = 22528; } }
        }
        int local = (b - base) * 1024 + threadIdx.x * 4;
        size_t g  = (size_t)b * 1024 + threadIdx.x * 4;
        float4 v = *(const float4*)(s + local);
        *(__nv_bfloat162*)(g_wall + g)     = __floats2bfloat162_rn(v.x, v.y);
        *(__nv_bfloat162*)(g_wall + g + 2) = __floats2bfloat162_rn(v.z, v.w);
    } else {
        int idx = (b - 26624) * 1024 + threadIdx.x * 4;   // 4 consecutive elements
        int bb = idx >> 19;
        int k  = idx & (ND - 1);
        const float* eb = a.e + bb * 3 * ND;
        float4 sh = *(const float4*)(eb + k);
        float4 sc = *(const float4*)(eb + ND + k);
        float4 zs = *(const float4*)(a.sz + idx);
        float4 za = *(const float4*)(a.az + idx);
        *(__nv_bfloat162*)(g_xsb + idx) =
            __floats2bfloat162_rn((1.0f + sc.x) * zs.x + sh.x, (1.0f + sc.y) * zs.y + sh.y);
        *(__nv_bfloat162*)(g_xsb + idx + 2) =
            __floats2bfloat162_rn((1.0f + sc.z) * zs.z + sh.z, (1.0f + sc.w) * zs.w + sh.w);
        *(__nv_bfloat162*)(g_xab + idx) =
            __floats2bfloat162_rn((1.0f + sc.x) * za.x + sh.x, (1.0f + sc.y) * za.y + sh.y);
        *(__nv_bfloat162*)(g_xab + idx + 2) =
            __floats2bfloat162_rn((1.0f + sc.z) * za.z + sh.z, (1.0f + sc.w) * za.w + sh.w);
    }
}

// ---------------------------------------------------------------------------
// bf16 GEMM via mma.sync — BK=32, 4-stage cp.async, 80B pitch, single sync.
// MODE 0: merged QKV (branch halves, N=3072, K=1024) + FUSED ROPE -> bf16 g_qkvb
// MODE 1: merged headproj (thirds q/k/v, N=1024, K=1024, fp16 head-major;
//         q third pre-scaled by 0.125 for attention)
// MODE 2: merged MLP1  (branch halves, N=4096, K=1024, gelu -> bf16, a_split)
// MODE 3: merged MLP2  (branch halves, N=1024, K=4096, residual fp32)
// MODE 4: out-proj     (N=1024, K=1024, bf16 out)
// ---------------------------------------------------------------------------
#define ROWB   80
#define STG    (128 * ROWB)        // 10240 B per operand-stage
#define STAGES 4
#define DSMEM_BYTES (2 * STAGES * STG)   // 81920

template<int MODE>
__global__ void __launch_bounds__(256) gemm_mma(
    const __nv_bfloat16* __restrict__ A0, const __nv_bfloat16* __restrict__ A1,
    const __nv_bfloat16* __restrict__ W0, const __nv_bfloat16* __restrict__ W1,
    const float* __restrict__ b0, const float* __restrict__ b1,
    void* __restrict__ C0, void* __restrict__ C1,
    const float* __restrict__ Z0, const float* __restrict__ Z1,
    const float* __restrict__ E)
{
    constexpr int N  = (MODE == 0) ? 3072 : (MODE == 2) ? 4096 : 1024;
    constexpr int K  = (MODE == 3) ? 4096 : 1024;
    constexpr int NK = K / 32;

    extern __shared__ char sm_[];
    const uint32_t Ab = smem_u32(sm_);
    const uint32_t Bb = Ab + STAGES * STG;

    int tid = threadIdx.x, lane = tid & 31, wid = tid >> 5;
    int wm = wid & 1, wn = wid >> 1;
    int my = blockIdx.y;
    int bn = blockIdx.x * 128;

    const __nv_bfloat16* A;
    const __nv_bfloat16* W;
    const float* bias;
    const float* Z = nullptr;
    void* C = nullptr;
    int bm, branch = 0;
    float qsc = 1.0f;

    if (MODE == 0) {
        branch = my >> 5;
        A = branch ? A1 : A0;  W = branch ? W1 : W0;
        bias = branch ? b1 : b0;
        bm = (my & 31) * 128;
    } else if (MODE == 1) {
        int third = my >> 6;
        A = A0 + (size_t)third * (BT * ND);
        W = W0 + (size_t)third * (ND * ND);
        bias = b0 + third * ND;
        C = (void*)((__half*)C0 + (size_t)third * (BT * ND));
        bm = (my & 63) * 128;
        if (third == 0) qsc = 0.125f;   // fold attention score scale into q
    } else if (MODE == 2) {
        branch = my >> 5;
        A = A0;  W = branch ? W1 : W0;  bias = branch ? b1 : b0;
        C = (void*)((__nv_bfloat16*)C0 + (size_t)branch * (BSq * D4));
        bm = (my & 31) * 128;
    } else if (MODE == 3) {
        branch = my >> 5;
        A = A0 + (size_t)branch * (BSq * D4);
        W = branch ? W1 : W0;  bias = branch ? b1 : b0;
        Z = branch ? Z1 : Z0;
        C = (void*)((float*)C0 + (size_t)branch * (BSq * ND));
        bm = (my & 31) * 128;
    } else {
        A = A0; W = W0; bias = b0; C = C0;
        bm = my * 128;
    }

    // --- global load geometry: each thread 16B x (2 rows A + 2 rows B) per stage
    int lr = tid >> 2, lc = tid & 3;
    int am0 = bm + lr, am1 = bm + lr + 64;
    int ar0 = (MODE == 2) ? (((am0 >> 9) << 10) + branch * NS + (am0 & (NS - 1))) : am0;
    int ar1 = (MODE == 2) ? (((am1 >> 9) << 10) + branch * NS + (am1 & (NS - 1))) : am1;
    const __nv_bfloat16* Ag0 = A + (size_t)ar0 * K + lc * 8;
    const __nv_bfloat16* Ag1 = A + (size_t)ar1 * K + lc * 8;
    const __nv_bfloat16* Wg0 = W + (size_t)(bn + lr) * K + lc * 8;
    const __nv_bfloat16* Wg1 = W + (size_t)(bn + lr + 64) * K + lc * 8;
    uint32_t dst0 = (uint32_t)(lr * ROWB + lc * 16);
    uint32_t dst1 = dst0 + 64 * ROWB;

    // --- compute-side smem fragment offsets
    uint32_t aoff = (uint32_t)((wm * 64 + (lane & 15)) * ROWB + (lane >> 4) * 16);
    uint32_t boff = (uint32_t)((wn * 32 + (lane >> 4) * 8 + (lane & 7)) * ROWB
                               + ((lane >> 3) & 1) * 16);

    float acc[4][4][4] = {};

    // prologue: stages 0..STAGES-2
#pragma unroll
    for (int s = 0; s < STAGES - 1; s++) {
        uint32_t a = Ab + s * STG, b = Bb + s * STG;
        int ke = s * 32;
        cp16(a + dst0, Ag0 + ke); cp16(a + dst1, Ag1 + ke);
        cp16(b + dst0, Wg0 + ke); cp16(b + dst1, Wg1 + ke);
        asm volatile("cp.async.commit_group;" ::: "memory");
    }

    for (int kt = 0; kt < NK; kt++) {
        asm volatile("cp.async.wait_group %0;" :: "n"(STAGES - 2) : "memory");
        __syncthreads();

        int j = kt + STAGES - 1;
        if (j < NK) {
            int sj = j % STAGES;
            uint32_t a = Ab + sj * STG, b = Bb + sj * STG;
            int ke = j * 32;
            cp16(a + dst0, Ag0 + ke); cp16(a + dst1, Ag1 + ke);
            cp16(b + dst0, Wg0 + ke); cp16(b + dst1, Wg1 + ke);
        }
        asm volatile("cp.async.commit_group;" ::: "memory");

        int s = kt % STAGES;
        uint32_t a0 = Ab + s * STG + aoff;
        uint32_t b0s = Bb + s * STG + boff;
#pragma unroll
        for (int ks = 0; ks < 2; ks++) {
            uint32_t af[4][4], bf[2][4];
#pragma unroll
            for (int mf = 0; mf < 4; mf++) ldm4(a0 + mf * 16 * ROWB + ks * 32, af[mf]);
#pragma unroll
            for (int nn = 0; nn < 2; nn++) ldm4(b0s + nn * 16 * ROWB + ks * 32, bf[nn]);
#pragma unroll
            for (int mf = 0; mf < 4; mf++)
#pragma unroll
                for (int nf = 0; nf < 4; nf++)
                    mma16816(acc[mf][nf], af[mf], &bf[nf >> 1][(nf & 1) * 2]);
        }
    }

    // --- epilogue: fragments -> global, fused bias + transform
    int gr = lane >> 2, gc = (lane & 3) * 2;
#pragma unroll
    for (int mf = 0; mf < 4; mf++) {
#pragma unroll
        for (int nf = 0; nf < 4; nf++) {
            float* c = acc[mf][nf];
            int n  = bn + wn * 32 + nf * 8 + gc;
            int m0 = bm + wm * 64 + mf * 16 + gr;
            float bn0 = bias[n], bn1 = bias[n + 1];
            float inv = 0.0f;
            if (MODE == 0) {
                inv = __expf(-6.238324625039508f * (float)(n & 1023) * (1.0f / 1024.0f));
            }
#pragma unroll
            for (int half = 0; half < 2; half++) {
                int m = m0 + half * 8;
                float v0 = c[half * 2]     + bn0;
                float v1 = c[half * 2 + 1] + bn1;
                if (MODE == 0) {
                    int sec   = n >> 10;                // 0=q, 1=k, 2=v
                    int s_pos = m & (NS - 1);
                    int bb    = m >> 9;
                    size_t dst = ((size_t)(bb << 10) + (size_t)branch * NS + s_pos) * ND
                                 + (n & 1023);
                    if (sec < 2) {
                        float th = (float)s_pos * inv;
                        float sn, cs;
                        __sincosf(th, &sn, &cs);
                        float re = v0 * cs - v1 * sn;
                        float im = v0 * sn + v1 * cs;
                        __nv_bfloat16* base = g_qkvb + (size_t)sec * (BT * ND);
                        *(__nv_bfloat162*)(base + dst) = __floats2bfloat162_rn(re, im);
                    } else {
                        *(__nv_bfloat162*)(g_qkvb + 2 * (size_t)BT * ND + dst) =
                            __floats2bfloat162_rn(v0, v1);
                    }
                } else if (MODE == 1) {
                    int b = m >> 10, t = m & (S2 - 1), h = n >> 6;
                    __half* dst = (__half*)C + ((size_t)(b * NH + h) * S2 + t) * NHD + (n & 63);
                    *(__half2*)dst = __floats2half2_rn(v0 * qsc, v1 * qsc);
                } else if (MODE == 2) {
                    float x = v0;
                    float gx = 0.5f * x * (1.0f + tanhf(0.7978845608028654f * (x + 0.044715f * x * x * x)));
                    x = v1;
                    float gy = 0.5f * x * (1.0f + tanhf(0.7978845608028654f * (x + 0.044715f * x * x * x)));
                    *(__nv_bfloat162*)((__nv_bfloat16*)C + (size_t)m * N + n) =
                        __floats2bfloat162_rn(gx, gy);
                } else if (MODE == 3) {
                    int b = m >> 9;
                    const float* ep = E + (size_t)b * 3 * ND + 2 * ND + n;
                    const float* zp = Z + (size_t)m * N + n;
                    *(float2*)((float*)C + (size_t)m * N + n) =
                        make_float2(zp[0] + v0 * ep[0], zp[1] + v1 * ep[1]);
                } else {
                    *(__nv_bfloat162*)((__nv_bfloat16*)C + (size_t)m * N + n) =
                        __floats2bfloat162_rn(v0, v1);
                }
            }
        }
    }
}

// ---------------------------------------------------------------------------
// Flash attention via fp16 mma.sync. One block per (b, h, 128 q-rows).
// 3-stage KV pipeline, single sync per iter, q pre-scaled, 3 CTAs/SM target.
// ---------------------------------------------------------------------------
#define AT_PITCH   144
#define AT_QB      (128 * AT_PITCH)        // 18432
#define AT_KVB     (64 * AT_PITCH)         // 9216
#define AT_SMEM    (AT_QB + 6 * AT_KVB)    // 73728

__global__ void __launch_bounds__(256, 3) attn_mma_kernel()
{
    extern __shared__ char sm_[];
    uint32_t Qb = smem_u32(sm_);
    uint32_t Kb = Qb + AT_QB;
    uint32_t Vb = Kb + 3 * AT_KVB;

    int b = blockIdx.z, h = blockIdx.y, qt = blockIdx.x;
    int tid = threadIdx.x, lane = tid & 31, wid = tid >> 5;

    const __half* qg = g_hh + ((size_t)(b * NH + h) * S2 + qt * 128) * NHD;
    const __half* kg = g_hh + (size_t)BT * ND + (size_t)(b * NH + h) * S2 * NHD;
    const __half* vg = g_hh + 2 * (size_t)BT * ND + (size_t)(b * NH + h) * S2 * NHD;

    // prologue: Q (1 group) + KV stages 0,1 (2 groups)
    for (int i = tid; i < 1024; i += 256) {
        int row = i >> 3, c = i & 7;
        cp16(Qb + row * AT_PITCH + c * 16, qg + row * 64 + c * 8);
    }
    asm volatile("cp.async.commit_group;" ::: "memory");

#pragma unroll
    for (int s = 0; s < 2; s++) {
        const __half* ks = kg + (size_t)s * 4096;
        const __half* vs = vg + (size_t)s * 4096;
        for (int i = tid; i < 512; i += 256) {
            int row = i >> 3, c = i & 7;
            cp16(Kb + s * AT_KVB + row * AT_PITCH + c * 16, ks + row * 64 + c * 8);
            cp16(Vb + s * AT_KVB + row * AT_PITCH + c * 16, vs + row * 64 + c * 8);
        }
        asm volatile("cp.async.commit_group;" ::: "memory");
    }

    uint32_t q_off    = Qb + (wid * 16 + (lane & 15)) * AT_PITCH + (lane >> 4) * 16;
    uint32_t k_rowpat = (lane >> 4) * 8 + (lane & 7);
    uint32_t k_colpat = ((lane >> 3) & 1) * 16;
    uint32_t v_rowpat = lane & 15;
    uint32_t v_colpat = ((lane >> 4) & 1) * 16;

    float o[8][4] = {};
    float mrow0 = -1e30f, mrow1 = -1e30f;
    float lrow0 = 0.f, lrow1 = 0.f;

    for (int kt = 0; kt < 16; kt++) {
        // wait: KV(kt) + Q complete; KV(kt+1) may remain in flight
        asm volatile("cp.async.wait_group 1;" ::: "memory");
        __syncthreads();

        // prefetch KV(kt+2) into slot (kt+2)%3 (consumed in iter kt-1; safe)
        int j = kt + 2;
        if (j < 16) {
            int sj = j % 3;
            const __half* ks = kg + (size_t)j * 4096;
            const __half* vs = vg + (size_t)j * 4096;
            for (int i = tid; i < 512; i += 256) {
                int row = i >> 3, c = i & 7;
                cp16(Kb + sj * AT_KVB + row * AT_PITCH + c * 16, ks + row * 64 + c * 8);
                cp16(Vb + sj * AT_KVB + row * AT_PITCH + c * 16, vs + row * 64 + c * 8);
            }
        }
        asm volatile("cp.async.commit_group;" ::: "memory");

        uint32_t ksm = Kb + (kt % 3) * AT_KVB;
        uint32_t vsm = Vb + (kt % 3) * AT_KVB;

        float s[8][4] = {};
#pragma unroll
        for (int kk = 0; kk < 4; kk++) {
            uint32_t qf[4];
            ldm4(q_off + kk * 32, qf);
#pragma unroll
            for (int nt = 0; nt < 4; nt++) {
                uint32_t kf[4];
                ldm4(ksm + (nt * 16 + k_rowpat) * AT_PITCH + k_colpat + kk * 32, kf);
                mma16816h(s[nt * 2],     qf, kf);
                mma16816h(s[nt * 2 + 1], qf, kf + 2);
            }
        }

        // online softmax (q pre-scaled; no score multiply needed)
        float mn0 = mrow0, mn1 = mrow1;
#pragma unroll
        for (int j2 = 0; j2 < 8; j2++) {
            mn0 = fmaxf(mn0, fmaxf(s[j2][0], s[j2][1]));
            mn1 = fmaxf(mn1, fmaxf(s[j2][2], s[j2][3]));
        }
        mn0 = fmaxf(mn0, __shfl_xor_sync(0xffffffffu, mn0, 1));
        mn0 = fmaxf(mn0, __shfl_xor_sync(0xffffffffu, mn0, 2));
        mn1 = fmaxf(mn1, __shfl_xor_sync(0xffffffffu, mn1, 1));
        mn1 = fmaxf(mn1, __shfl_xor_sync(0xffffffffu, mn1, 2));
        float al0 = __expf(mrow0 - mn0), al1 = __expf(mrow1 - mn1);
        mrow0 = mn0; mrow1 = mn1;

        float ls0 = 0.f, ls1 = 0.f;
        uint32_t p[8][2];
#pragma unroll
        for (int j2 = 0; j2 < 8; j2++) {
            float p0 = __expf(s[j2][0] - mn0), p1 = __expf(s[j2][1] - mn0);
            float p2 = __expf(s[j2][2] - mn1), p3 = __expf(s[j2][3] - mn1);
            ls0 += p0 + p1; ls1 += p2 + p3;
            p[j2][0] = h2pack(p0, p1);
            p[j2][1] = h2pack(p2, p3);
        }
        lrow0 = lrow0 * al0 + ls0;
        lrow1 = lrow1 * al1 + ls1;
#pragma unroll
        for (int j2 = 0; j2 < 8; j2++) {
            o[j2][0] *= al0; o[j2][1] *= al0; o[j2][2] *= al1; o[j2][3] *= al1;
        }

#pragma unroll
        for (int kp = 0; kp < 4; kp++) {
            uint32_t af[4] = { p[2 * kp][0], p[2 * kp][1], p[2 * kp + 1][0], p[2 * kp + 1][1] };
#pragma unroll
            for (int nt = 0; nt < 4; nt++) {
                uint32_t vf[4];
                ldm4t(vsm + (kp * 16 + v_rowpat) * AT_PITCH + nt * 32 + v_colpat, vf);
                mma16816h(o[nt * 2],     af, vf);
                mma16816h(o[nt * 2 + 1], af, vf + 2);
            }
        }
    }

    float lt0 = lrow0;
    lt0 += __shfl_xor_sync(0xffffffffu, lt0, 1);
    lt0 += __shfl_xor_sync(0xffffffffu, lt0, 2);
    float lt1 = lrow1;
    lt1 += __shfl_xor_sync(0xffffffffu, lt1, 1);
    lt1 += __shfl_xor_sync(0xffffffffu, lt1, 2);
    float inv0 = 1.0f / lt0, inv1 = 1.0f / lt1;

    int gr = lane >> 2, qc = (lane & 3) * 2;
    int r0 = qt * 128 + wid * 16 + gr;
    size_t base0 = ((size_t)b * S2 + r0) * ND + h * 64 + qc;
    size_t base1 = base0 + (size_t)8 * ND;
#pragma unroll
    for (int j = 0; j < 8; j++) {
        *(__nv_bfloat162*)&g_ob[base0 + j * 8] =
            __floats2bfloat162_rn(o[j][0] * inv0, o[j][1] * inv0);
        *(__nv_bfloat162*)&g_ob[base1 + j * 8] =
            __floats2bfloat162_rn(o[j][2] * inv1, o[j][3] * inv1);
    }
}

// ---------------------------------------------------------------------------
// Launch sequence
// ---------------------------------------------------------------------------
extern "C" void kernel_launch(void* const* d_in, const int* in_sizes, int n_in,
                              void* d_out, int out_size)
{
    const float* state_z    = (const float*)d_in[0];
    const float* action_z   = (const float*)d_in[1];
    const float* e          = (const float*)d_in[2];
    const float* qkv_s_w    = (const float*)d_in[3];
    const float* qkv_s_b    = (const float*)d_in[4];
    const float* qkv_a_w    = (const float*)d_in[5];
    const float* qkv_a_b    = (const float*)d_in[6];
    const float* attn_in_w  = (const float*)d_in[7];
    const float* attn_in_b  = (const float*)d_in[8];
    const float* attn_out_w = (const float*)d_in[9];
    const float* attn_out_b = (const float*)d_in[10];
    const float* mw1s       = (const float*)d_in[11];
    const float* mb1s       = (const float*)d_in[12];
    const float* mw2s       = (const float*)d_in[13];
    const float* mb2s       = (const float*)d_in[14];
    const float* mw1a       = (const float*)d_in[15];
    const float* mb1a       = (const float*)d_in[16];
    const float* mw2a       = (const float*)d_in[17];
    const float* mb2a       = (const float*)d_in[18];
    float* out = (float*)d_out;

    __nv_bfloat16 *wall, *xsb, *xab, *qkvb, *ob, *yb, *h1b;
    __half *hh;
    cudaGetSymbolAddress((void**)&wall, g_wall);
    cudaGetSymbolAddress((void**)&xsb,  g_xsb);
    cudaGetSymbolAddress((void**)&xab,  g_xab);
    cudaGetSymbolAddress((void**)&qkvb, g_qkvb);
    cudaGetSymbolAddress((void**)&hh,   g_hh);
    cudaGetSymbolAddress((void**)&ob,   g_ob);
    cudaGetSymbolAddress((void**)&yb,   g_yb);
    cudaGetSymbolAddress((void**)&h1b,  g_h1b);

    cudaFuncSetAttribute(gemm_mma<0>, cudaFuncAttributeMaxDynamicSharedMemorySize, DSMEM_BYTES);
    cudaFuncSetAttribute(gemm_mma<1>, cudaFuncAttributeMaxDynamicSharedMemorySize, DSMEM_BYTES);
    cudaFuncSetAttribute(gemm_mma<2>, cudaFuncAttributeMaxDynamicSharedMemorySize, DSMEM_BYTES);
    cudaFuncSetAttribute(gemm_mma<3>, cudaFuncAttributeMaxDynamicSharedMemorySize, DSMEM_BYTES);
    cudaFuncSetAttribute(gemm_mma<4>, cudaFuncAttributeMaxDynamicSharedMemorySize, DSMEM_BYTES);
    cudaFuncSetAttribute(attn_mma_kernel, cudaFuncAttributeMaxDynamicSharedMemorySize, AT_SMEM);

    // 1. prep: weight conversion + modulation (single kernel)
    PrepArgs pa;
    pa.src[0] = qkv_s_w;  pa.src[1] = qkv_a_w;  pa.src[2] = attn_in_w;
    pa.src[3] = attn_out_w; pa.src[4] = mw1s;   pa.src[5] = mw2s;
    pa.src[6] = mw1a;     pa.src[7] = mw2a;
    pa.sz = state_z; pa.az = action_z; pa.e = e;
    prep_kernel<<<30720, 256>>>(pa);

    // 2. merged QKV GEMM with fused RoPE+concat -> g_qkvb (bf16)
    dim3 gq(D3 / 128, 64);
    gemm_mma<0><<<gq, 256, DSMEM_BYTES>>>(xsb, xab, wall + O_WQS, wall + O_WQA,
                                          qkv_s_b, qkv_a_b, nullptr, nullptr,
                                          nullptr, nullptr, nullptr);

    // 3. merged head projections (thirds q,k,v) -> fp16 head-major g_hh
    dim3 gh(ND / 128, 192);
    gemm_mma<1><<<gh, 256, DSMEM_BYTES>>>(qkvb, nullptr, wall + O_WAI, nullptr,
                                          attn_in_b, nullptr, hh, nullptr,
                                          nullptr, nullptr, nullptr);

    // 4. attention
    dim3 ga(S2 / 128, NH, NB);
    attn_mma_kernel<<<ga, 256, AT_SMEM>>>();

    // 5. output projection -> bf16
    dim3 go(ND / 128, 64);
    gemm_mma<4><<<go, 256, DSMEM_BYTES>>>(ob, nullptr, wall + O_WAO, nullptr,
                                          attn_out_b, nullptr, yb, nullptr,
                                          nullptr, nullptr, nullptr);

    // 6. merged MLP1 (gelu) -> g_h1b (both branches)
    dim3 g1(D4 / 128, 64);
    gemm_mma<2><<<g1, 256, DSMEM_BYTES>>>(yb, nullptr, wall + O_W1S, wall + O_W1A,
                                          mb1s, mb1a, h1b, nullptr,
                                          nullptr, nullptr, nullptr);

    // 7. merged MLP2 (gated residual) -> out
    dim3 g2(ND / 128, 64);
    gemm_mma<3><<<g2, 256, DSMEM_BYTES>>>(h1b, nullptr, wall + O_W2S, wall + O_W2A,
                                          mb2s, mb2a, out, nullptr,
                                          state_z, action_z, e);
}

// round 16
// speedup vs baseline: 1.2038x; 1.0120x over previous
#include <cuda_runtime.h>
#include <cuda_bf16.h>
#include <cuda_fp16.h>
#include <math.h>
#include <stdint.h>

#define NB   8
#define NS   512
#define ND   1024
#define NH   16
#define NHD  64
#define S2   1024
#define BSq  4096
#define BT   8192
#define D3   3072
#define D4   4096

// weight layout inside g_wall (element offsets)
#define O_WQS 0u
#define O_WQA 3145728u
#define O_WAI 6291456u
#define O_WAO 9437184u
#define O_W1S 10485760u
#define O_W2S 14680064u
#define O_W1A 18874368u
#define O_W2A 23068672u
#define WALL_N 27262976u

// ---------------------------------------------------------------------------
// Scratch (device globals)
// ---------------------------------------------------------------------------
__device__ __nv_bfloat16 g_wall[WALL_N];
__device__ __nv_bfloat16 g_xsb [BSq * ND];
__device__ __nv_bfloat16 g_xab [BSq * ND];
__device__ __nv_bfloat16 g_qkvb[3 * BT * ND];     // roped q,k | v (token-major)
__device__ __half        g_hh  [3 * BT * ND];     // fp16 head-major q,k,v (q pre-scaled)
__device__ __nv_bfloat16 g_ob  [BT * ND];
__device__ __nv_bfloat16 g_yb  [BT * ND];
__device__ __nv_bfloat16 g_h1b [2 * BSq * D4];

// ---------------------------------------------------------------------------
// PTX helpers (sm_80-era only)
// ---------------------------------------------------------------------------
__device__ __forceinline__ uint32_t smem_u32(const void* p) {
    uint32_t a;
    asm("{ .reg .u64 t; cvta.to.shared.u64 t, %1; cvt.u32.u64 %0, t; }"
        : "=r"(a) : "l"(p));
    return a;
}

__device__ __forceinline__ void cp16(uint32_t dst, const void* src) {
    asm volatile("cp.async.cg.shared.global [%0], [%1], 16;"
                 :: "r"(dst), "l"(src) : "memory");
}

__device__ __forceinline__ void ldm4(uint32_t addr, uint32_t* r) {
    asm volatile("ldmatrix.sync.aligned.m8n8.x4.shared.b16 {%0,%1,%2,%3}, [%4];"
                 : "=r"(r[0]), "=r"(r[1]), "=r"(r[2]), "=r"(r[3]) : "r"(addr));
}

__device__ __forceinline__ void ldm4t(uint32_t addr, uint32_t* r) {
    asm volatile("ldmatrix.sync.aligned.m8n8.x4.trans.shared.b16 {%0,%1,%2,%3}, [%4];"
                 : "=r"(r[0]), "=r"(r[1]), "=r"(r[2]), "=r"(r[3]) : "r"(addr));
}

__device__ __forceinline__ void mma16816(float* c, const uint32_t* a, const uint32_t* b) {
    asm volatile(
        "mma.sync.aligned.m16n8k16.row.col.f32.bf16.bf16.f32 "
        "{%0,%1,%2,%3}, {%4,%5,%6,%7}, {%8,%9}, {%0,%1,%2,%3};"
        : "+f"(c[0]), "+f"(c[1]), "+f"(c[2]), "+f"(c[3])
        : "r"(a[0]), "r"(a[1]), "r"(a[2]), "r"(a[3]), "r"(b[0]), "r"(b[1]));
}

__device__ __forceinline__ void mma16816h(float* c, const uint32_t* a, const uint32_t* b) {
    asm volatile(
        "mma.sync.aligned.m16n8k16.row.col.f32.f16.f16.f32 "
        "{%0,%1,%2,%3}, {%4,%5,%6,%7}, {%8,%9}, {%0,%1,%2,%3};"
        : "+f"(c[0]), "+f"(c[1]), "+f"(c[2]), "+f"(c[3])
        : "r"(a[0]), "r"(a[1]), "r"(a[2]), "r"(a[3]), "r"(b[0]), "r"(b[1]));
}

__device__ __forceinline__ uint32_t h2pack(float a, float b) {
    __half2 t = __floats2half2_rn(a, b);
    return *reinterpret_cast<uint32_t*>(&t);
}

// Fast gelu (tanh approx): 0.5x(1+tanh(u)) == x * sigmoid(2u)
__device__ __forceinline__ float gelu_fast(float x) {
    float t = __expf(-1.5957691216057308f * (x + 0.044715f * x * x * x));
    return __fdividef(x, 1.0f + t);
}

// ---------------------------------------------------------------------------
// Prep kernel: weight fp32->bf16 conversion (blocks 0..26623) +
// modulation (blocks 26624..30719, vectorized x4)
// ---------------------------------------------------------------------------
struct PrepArgs {
    const float* src[8];
    const float* sz;
    const float* az;
    const float* e;
};

__global__ void prep_kernel(PrepArgs a) {
    int b = blockIdx.x;
    if (b < 26624) {
        const float* s;
        int base;
        if (b < 10240) {
            if (b < 6144) { if (b < 3072) { s = a.src[0]; base = 0; }
                            else          { s = a.src[1]; base = 3072; } }
            else          { if (b < 9216) { s = a.src[2]; base = 6144; }
                            else          { s = a.src[3]; base = 9216; } }
        } else {
            if (b < 18432) { if (b < 14336) { s = a.src[4]; base = 10240; }
                             else           { s = a.src[5]; base = 14336; } }
            else           { if (b < 22528) { s = a.src[6]; base = 18432; }
                             else           { s = a.src[7]; base = 22528; } }
        }
        int local = (b - base) * 1024 + threadIdx.x * 4;
        size_t g  = (size_t)b * 1024 + threadIdx.x * 4;
        float4 v = *(const float4*)(s + local);
        *(__nv_bfloat162*)(g_wall + g)     = __floats2bfloat162_rn(v.x, v.y);
        *(__nv_bfloat162*)(g_wall + g + 2) = __floats2bfloat162_rn(v.z, v.w);
    } else {
        int idx = (b - 26624) * 1024 + threadIdx.x * 4;   // 4 consecutive elements
        int bb = idx >> 19;
        int k  = idx & (ND - 1);
        const float* eb = a.e + bb * 3 * ND;
        float4 sh = *(const float4*)(eb + k);
        float4 sc = *(const float4*)(eb + ND + k);
        float4 zs = *(const float4*)(a.sz + idx);
        float4 za = *(const float4*)(a.az + idx);
        *(__nv_bfloat162*)(g_xsb + idx) =
            __floats2bfloat162_rn((1.0f + sc.x) * zs.x + sh.x, (1.0f + sc.y) * zs.y + sh.y);
        *(__nv_bfloat162*)(g_xsb + idx + 2) =
            __floats2bfloat162_rn((1.0f + sc.z) * zs.z + sh.z, (1.0f + sc.w) * zs.w + sh.w);
        *(__nv_bfloat162*)(g_xab + idx) =
            __floats2bfloat162_rn((1.0f + sc.x) * za.x + sh.x, (1.0f + sc.y) * za.y + sh.y);
        *(__nv_bfloat162*)(g_xab + idx + 2) =
            __floats2bfloat162_rn((1.0f + sc.z) * za.z + sh.z, (1.0f + sc.w) * za.w + sh.w);
    }
}

// ---------------------------------------------------------------------------
// bf16 GEMM via mma.sync — BK=32, 4-stage cp.async, 80B pitch, single sync.
// MODE 0: merged QKV (branch halves, N=3072, K=1024) + FUSED ROPE -> bf16 g_qkvb
// MODE 1: merged headproj (thirds q/k/v, N=1024, K=1024, fp16 head-major;
//         q third pre-scaled by 0.125 for attention)
// MODE 2: merged MLP1  (branch halves, N=4096, K=1024, fast gelu -> bf16, a_split)
// MODE 3: merged MLP2  (branch halves, N=1024, K=4096, residual fp32)
// MODE 4: out-proj     (N=1024, K=1024, bf16 out)
// ---------------------------------------------------------------------------
#define ROWB   80
#define STG    (128 * ROWB)        // 10240 B per operand-stage
#define STAGES 4
#define DSMEM_BYTES (2 * STAGES * STG)   // 81920

template<int MODE>
__global__ void __launch_bounds__(256) gemm_mma(
    const __nv_bfloat16* __restrict__ A0, const __nv_bfloat16* __restrict__ A1,
    const __nv_bfloat16* __restrict__ W0, const __nv_bfloat16* __restrict__ W1,
    const float* __restrict__ b0, const float* __restrict__ b1,
    void* __restrict__ C0, void* __restrict__ C1,
    const float* __restrict__ Z0, const float* __restrict__ Z1,
    const float* __restrict__ E)
{
    constexpr int N  = (MODE == 0) ? 3072 : (MODE == 2) ? 4096 : 1024;
    constexpr int K  = (MODE == 3) ? 4096 : 1024;
    constexpr int NK = K / 32;

    extern __shared__ char sm_[];
    const uint32_t Ab = smem_u32(sm_);
    const uint32_t Bb = Ab + STAGES * STG;

    int tid = threadIdx.x, lane = tid & 31, wid = tid >> 5;
    int wm = wid & 1, wn = wid >> 1;
    int my = blockIdx.y;
    int bn = blockIdx.x * 128;

    const __nv_bfloat16* A;
    const __nv_bfloat16* W;
    const float* bias;
    const float* Z = nullptr;
    void* C = nullptr;
    int bm, branch = 0;
    float qsc = 1.0f;

    if (MODE == 0) {
        branch = my >> 5;
        A = branch ? A1 : A0;  W = branch ? W1 : W0;
        bias = branch ? b1 : b0;
        bm = (my & 31) * 128;
    } else if (MODE == 1) {
        int third = my >> 6;
        A = A0 + (size_t)third * (BT * ND);
        W = W0 + (size_t)third * (ND * ND);
        bias = b0 + third * ND;
        C = (void*)((__half*)C0 + (size_t)third * (BT * ND));
        bm = (my & 63) * 128;
        if (third == 0) qsc = 0.125f;   // fold attention score scale into q
    } else if (MODE == 2) {
        branch = my >> 5;
        A = A0;  W = branch ? W1 : W0;  bias = branch ? b1 : b0;
        C = (void*)((__nv_bfloat16*)C0 + (size_t)branch * (BSq * D4));
        bm = (my & 31) * 128;
    } else if (MODE == 3) {
        branch = my >> 5;
        A = A0 + (size_t)branch * (BSq * D4);
        W = branch ? W1 : W0;  bias = branch ? b1 : b0;
        Z = branch ? Z1 : Z0;
        C = (void*)((float*)C0 + (size_t)branch * (BSq * ND));
        bm = (my & 31) * 128;
    } else {
        A = A0; W = W0; bias = b0; C = C0;
        bm = my * 128;
    }

    // --- global load geometry: each thread 16B x (2 rows A + 2 rows B) per stage
    int lr = tid >> 2, lc = tid & 3;
    int am0 = bm + lr, am1 = bm + lr + 64;
    int ar0 = (MODE == 2) ? (((am0 >> 9) << 10) + branch * NS + (am0 & (NS - 1))) : am0;
    int ar1 = (MODE == 2) ? (((am1 >> 9) << 10) + branch * NS + (am1 & (NS - 1))) : am1;
    const __nv_bfloat16* Ag0 = A + (size_t)ar0 * K + lc * 8;
    const __nv_bfloat16* Ag1 = A + (size_t)ar1 * K + lc * 8;
    const __nv_bfloat16* Wg0 = W + (size_t)(bn + lr) * K + lc * 8;
    const __nv_bfloat16* Wg1 = W + (size_t)(bn + lr + 64) * K + lc * 8;
    uint32_t dst0 = (uint32_t)(lr * ROWB + lc * 16);
    uint32_t dst1 = dst0 + 64 * ROWB;

    // --- compute-side smem fragment offsets
    uint32_t aoff = (uint32_t)((wm * 64 + (lane & 15)) * ROWB + (lane >> 4) * 16);
    uint32_t boff = (uint32_t)((wn * 32 + (lane >> 4) * 8 + (lane & 7)) * ROWB
                               + ((lane >> 3) & 1) * 16);

    float acc[4][4][4] = {};

    // prologue: stages 0..STAGES-2
#pragma unroll
    for (int s = 0; s < STAGES - 1; s++) {
        uint32_t a = Ab + s * STG, b = Bb + s * STG;
        int ke = s * 32;
        cp16(a + dst0, Ag0 + ke); cp16(a + dst1, Ag1 + ke);
        cp16(b + dst0, Wg0 + ke); cp16(b + dst1, Wg1 + ke);
        asm volatile("cp.async.commit_group;" ::: "memory");
    }

    for (int kt = 0; kt < NK; kt++) {
        asm volatile("cp.async.wait_group %0;" :: "n"(STAGES - 2) : "memory");
        __syncthreads();

        int j = kt + STAGES - 1;
        if (j < NK) {
            int sj = j % STAGES;
            uint32_t a = Ab + sj * STG, b = Bb + sj * STG;
            int ke = j * 32;
            cp16(a + dst0, Ag0 + ke); cp16(a + dst1, Ag1 + ke);
            cp16(b + dst0, Wg0 + ke); cp16(b + dst1, Wg1 + ke);
        }
        asm volatile("cp.async.commit_group;" ::: "memory");

        int s = kt % STAGES;
        uint32_t a0 = Ab + s * STG + aoff;
        uint32_t b0s = Bb + s * STG + boff;
#pragma unroll
        for (int ks = 0; ks < 2; ks++) {
            uint32_t af[4][4], bf[2][4];
#pragma unroll
            for (int mf = 0; mf < 4; mf++) ldm4(a0 + mf * 16 * ROWB + ks * 32, af[mf]);
#pragma unroll
            for (int nn = 0; nn < 2; nn++) ldm4(b0s + nn * 16 * ROWB + ks * 32, bf[nn]);
#pragma unroll
            for (int mf = 0; mf < 4; mf++)
#pragma unroll
                for (int nf = 0; nf < 4; nf++)
                    mma16816(acc[mf][nf], af[mf], &bf[nf >> 1][(nf & 1) * 2]);
        }
    }

    // --- epilogue: fragments -> global, fused bias + transform
    int gr = lane >> 2, gc = (lane & 3) * 2;
#pragma unroll
    for (int mf = 0; mf < 4; mf++) {
#pragma unroll
        for (int nf = 0; nf < 4; nf++) {
            float* c = acc[mf][nf];
            int n  = bn + wn * 32 + nf * 8 + gc;
            int m0 = bm + wm * 64 + mf * 16 + gr;
            float bn0 = bias[n], bn1 = bias[n + 1];
            float inv = 0.0f;
            if (MODE == 0) {
                inv = __expf(-6.238324625039508f * (float)(n & 1023) * (1.0f / 1024.0f));
            }
#pragma unroll
            for (int half = 0; half < 2; half++) {
                int m = m0 + half * 8;
                float v0 = c[half * 2]     + bn0;
                float v1 = c[half * 2 + 1] + bn1;
                if (MODE == 0) {
                    int sec   = n >> 10;                // 0=q, 1=k, 2=v
                    int s_pos = m & (NS - 1);
                    int bb    = m >> 9;
                    size_t dst = ((size_t)(bb << 10) + (size_t)branch * NS + s_pos) * ND
                                 + (n & 1023);
                    if (sec < 2) {
                        float th = (float)s_pos * inv;
                        float sn, cs;
                        __sincosf(th, &sn, &cs);
                        float re = v0 * cs - v1 * sn;
                        float im = v0 * sn + v1 * cs;
                        __nv_bfloat16* base = g_qkvb + (size_t)sec * (BT * ND);
                        *(__nv_bfloat162*)(base + dst) = __floats2bfloat162_rn(re, im);
                    } else {
                        *(__nv_bfloat162*)(g_qkvb + 2 * (size_t)BT * ND + dst) =
                            __floats2bfloat162_rn(v0, v1);
                    }
                } else if (MODE == 1) {
                    int b = m >> 10, t = m & (S2 - 1), h = n >> 6;
                    __half* dst = (__half*)C + ((size_t)(b * NH + h) * S2 + t) * NHD + (n & 63);
                    *(__half2*)dst = __floats2half2_rn(v0 * qsc, v1 * qsc);
                } else if (MODE == 2) {
                    *(__nv_bfloat162*)((__nv_bfloat16*)C + (size_t)m * N + n) =
                        __floats2bfloat162_rn(gelu_fast(v0), gelu_fast(v1));
                } else if (MODE == 3) {
                    int b = m >> 9;
                    const float* ep = E + (size_t)b * 3 * ND + 2 * ND + n;
                    const float* zp = Z + (size_t)m * N + n;
                    *(float2*)((float*)C + (size_t)m * N + n) =
                        make_float2(zp[0] + v0 * ep[0], zp[1] + v1 * ep[1]);
                } else {
                    *(__nv_bfloat162*)((__nv_bfloat16*)C + (size_t)m * N + n) =
                        __floats2bfloat162_rn(v0, v1);
                }
            }
        }
    }
}

// ---------------------------------------------------------------------------
// Flash attention via fp16 mma.sync. One block per (b, h, 128 q-rows).
// 3-stage KV pipeline, single sync per iter, q pre-scaled, Q fragments
// hoisted to registers (loaded once at kt=0).
// ---------------------------------------------------------------------------
#define AT_PITCH   144
#define AT_QB      (128 * AT_PITCH)        // 18432
#define AT_KVB     (64 * AT_PITCH)         // 9216
#define AT_SMEM    (AT_QB + 6 * AT_KVB)    // 73728

__global__ void __launch_bounds__(256) attn_mma_kernel()
{
    extern __shared__ char sm_[];
    uint32_t Qb = smem_u32(sm_);
    uint32_t Kb = Qb + AT_QB;
    uint32_t Vb = Kb + 3 * AT_KVB;

    int b = blockIdx.z, h = blockIdx.y, qt = blockIdx.x;
    int tid = threadIdx.x, lane = tid & 31, wid = tid >> 5;

    const __half* qg = g_hh + ((size_t)(b * NH + h) * S2 + qt * 128) * NHD;
    const __half* kg = g_hh + (size_t)BT * ND + (size_t)(b * NH + h) * S2 * NHD;
    const __half* vg = g_hh + 2 * (size_t)BT * ND + (size_t)(b * NH + h) * S2 * NHD;

    // prologue: Q (1 group) + KV stages 0,1 (2 groups)
    for (int i = tid; i < 1024; i += 256) {
        int row = i >> 3, c = i & 7;
        cp16(Qb + row * AT_PITCH + c * 16, qg + row * 64 + c * 8);
    }
    asm volatile("cp.async.commit_group;" ::: "memory");

#pragma unroll
    for (int s = 0; s < 2; s++) {
        const __half* ks = kg + (size_t)s * 4096;
        const __half* vs = vg + (size_t)s * 4096;
        for (int i = tid; i < 512; i += 256) {
            int row = i >> 3, c = i & 7;
            cp16(Kb + s * AT_KVB + row * AT_PITCH + c * 16, ks + row * 64 + c * 8);
            cp16(Vb + s * AT_KVB + row * AT_PITCH + c * 16, vs + row * 64 + c * 8);
        }
        asm volatile("cp.async.commit_group;" ::: "memory");
    }

    uint32_t q_off    = Qb + (wid * 16 + (lane & 15)) * AT_PITCH + (lane >> 4) * 16;
    uint32_t k_rowpat = (lane >> 4) * 8 + (lane & 7);
    uint32_t k_colpat = ((lane >> 3) & 1) * 16;
    uint32_t v_rowpat = lane & 15;
    uint32_t v_colpat = ((lane >> 4) & 1) * 16;

    uint32_t qf[4][4];       // hoisted Q fragments (invariant over kt)
    float o[8][4] = {};
    float mrow0 = -1e30f, mrow1 = -1e30f;
    float lrow0 = 0.f, lrow1 = 0.f;

    for (int kt = 0; kt < 16; kt++) {
        // wait: Q + KV(kt) complete; KV(kt+1) may remain in flight
        asm volatile("cp.async.wait_group 1;" ::: "memory");
        __syncthreads();

        if (kt == 0) {
#pragma unroll
            for (int kk = 0; kk < 4; kk++) ldm4(q_off + kk * 32, qf[kk]);
        }

        // prefetch KV(kt+2) into slot (kt+2)%3 (consumed in iter kt-1; safe)
        int j = kt + 2;
        if (j < 16) {
            int sj = j % 3;
            const __half* ks = kg + (size_t)j * 4096;
            const __half* vs = vg + (size_t)j * 4096;
            for (int i = tid; i < 512; i += 256) {
                int row = i >> 3, c = i & 7;
                cp16(Kb + sj * AT_KVB + row * AT_PITCH + c * 16, ks + row * 64 + c * 8);
                cp16(Vb + sj * AT_KVB + row * AT_PITCH + c * 16, vs + row * 64 + c * 8);
            }
        }
        asm volatile("cp.async.commit_group;" ::: "memory");

        uint32_t ksm = Kb + (kt % 3) * AT_KVB;
        uint32_t vsm = Vb + (kt % 3) * AT_KVB;

        float s[8][4] = {};
#pragma unroll
        for (int kk = 0; kk < 4; kk++) {
#pragma unroll
            for (int nt = 0; nt < 4; nt++) {
                uint32_t kf[4];
                ldm4(ksm + (nt * 16 + k_rowpat) * AT_PITCH + k_colpat + kk * 32, kf);
                mma16816h(s[nt * 2],     qf[kk], kf);
                mma16816h(s[nt * 2 + 1], qf[kk], kf + 2);
            }
        }

        // online softmax (q pre-scaled; no score multiply needed)
        float mn0 = mrow0, mn1 = mrow1;
#pragma unroll
        for (int j2 = 0; j2 < 8; j2++) {
            mn0 = fmaxf(mn0, fmaxf(s[j2][0], s[j2][1]));
            mn1 = fmaxf(mn1, fmaxf(s[j2][2], s[j2][3]));
        }
        mn0 = fmaxf(mn0, __shfl_xor_sync(0xffffffffu, mn0, 1));
        mn0 = fmaxf(mn0, __shfl_xor_sync(0xffffffffu, mn0, 2));
        mn1 = fmaxf(mn1, __shfl_xor_sync(0xffffffffu, mn1, 1));
        mn1 = fmaxf(mn1, __shfl_xor_sync(0xffffffffu, mn1, 2));
        float al0 = __expf(mrow0 - mn0), al1 = __expf(mrow1 - mn1);
        mrow0 = mn0; mrow1 = mn1;

        float ls0 = 0.f, ls1 = 0.f;
        uint32_t p[8][2];
#pragma unroll
        for (int j2 = 0; j2 < 8; j2++) {
            float p0 = __expf(s[j2][0] - mn0), p1 = __expf(s[j2][1] - mn0);
            float p2 = __expf(s[j2][2] - mn1), p3 = __expf(s[j2][3] - mn1);
            ls0 += p0 + p1; ls1 += p2 + p3;
            p[j2][0] = h2pack(p0, p1);
            p[j2][1] = h2pack(p2, p3);
        }
        lrow0 = lrow0 * al0 + ls0;
        lrow1 = lrow1 * al1 + ls1;
#pragma unroll
        for (int j2 = 0; j2 < 8; j2++) {
            o[j2][0] *= al0; o[j2][1] *= al0; o[j2][2] *= al1; o[j2][3] *= al1;
        }

#pragma unroll
        for (int kp = 0; kp < 4; kp++) {
            uint32_t af[4] = { p[2 * kp][0], p[2 * kp][1], p[2 * kp + 1][0], p[2 * kp + 1][1] };
#pragma unroll
            for (int nt = 0; nt < 4; nt++) {
                uint32_t vf[4];
                ldm4t(vsm + (kp * 16 + v_rowpat) * AT_PITCH + nt * 32 + v_colpat, vf);
                mma16816h(o[nt * 2],     af, vf);
                mma16816h(o[nt * 2 + 1], af, vf + 2);
            }
        }
    }

    float lt0 = lrow0;
    lt0 += __shfl_xor_sync(0xffffffffu, lt0, 1);
    lt0 += __shfl_xor_sync(0xffffffffu, lt0, 2);
    float lt1 = lrow1;
    lt1 += __shfl_xor_sync(0xffffffffu, lt1, 1);
    lt1 += __shfl_xor_sync(0xffffffffu, lt1, 2);
    float inv0 = 1.0f / lt0, inv1 = 1.0f / lt1;

    int gr = lane >> 2, qc = (lane & 3) * 2;
    int r0 = qt * 128 + wid * 16 + gr;
    size_t base0 = ((size_t)b * S2 + r0) * ND + h * 64 + qc;
    size_t base1 = base0 + (size_t)8 * ND;
#pragma unroll
    for (int j = 0; j < 8; j++) {
        *(__nv_bfloat162*)&g_ob[base0 + j * 8] =
            __floats2bfloat162_rn(o[j][0] * inv0, o[j][1] * inv0);
        *(__nv_bfloat162*)&g_ob[base1 + j * 8] =
            __floats2bfloat162_rn(o[j][2] * inv1, o[j][3] * inv1);
    }
}

// ---------------------------------------------------------------------------
// Launch sequence
// ---------------------------------------------------------------------------
extern "C" void kernel_launch(void* const* d_in, const int* in_sizes, int n_in,
                              void* d_out, int out_size)
{
    const float* state_z    = (const float*)d_in[0];
    const float* action_z   = (const float*)d_in[1];
    const float* e          = (const float*)d_in[2];
    const float* qkv_s_w    = (const float*)d_in[3];
    const float* qkv_s_b    = (const float*)d_in[4];
    const float* qkv_a_w    = (const float*)d_in[5];
    const float* qkv_a_b    = (const float*)d_in[6];
    const float* attn_in_w  = (const float*)d_in[7];
    const float* attn_in_b  = (const float*)d_in[8];
    const float* attn_out_w = (const float*)d_in[9];
    const float* attn_out_b = (const float*)d_in[10];
    const float* mw1s       = (const float*)d_in[11];
    const float* mb1s       = (const float*)d_in[12];
    const float* mw2s       = (const float*)d_in[13];
    const float* mb2s       = (const float*)d_in[14];
    const float* mw1a       = (const float*)d_in[15];
    const float* mb1a       = (const float*)d_in[16];
    const float* mw2a       = (const float*)d_in[17];
    const float* mb2a       = (const float*)d_in[18];
    float* out = (float*)d_out;

    __nv_bfloat16 *wall, *xsb, *xab, *qkvb, *ob, *yb, *h1b;
    __half *hh;
    cudaGetSymbolAddress((void**)&wall, g_wall);
    cudaGetSymbolAddress((void**)&xsb,  g_xsb);
    cudaGetSymbolAddress((void**)&xab,  g_xab);
    cudaGetSymbolAddress((void**)&qkvb, g_qkvb);
    cudaGetSymbolAddress((void**)&hh,   g_hh);
    cudaGetSymbolAddress((void**)&ob,   g_ob);
    cudaGetSymbolAddress((void**)&yb,   g_yb);
    cudaGetSymbolAddress((void**)&h1b,  g_h1b);

    cudaFuncSetAttribute(gemm_mma<0>, cudaFuncAttributeMaxDynamicSharedMemorySize, DSMEM_BYTES);
    cudaFuncSetAttribute(gemm_mma<1>, cudaFuncAttributeMaxDynamicSharedMemorySize, DSMEM_BYTES);
    cudaFuncSetAttribute(gemm_mma<2>, cudaFuncAttributeMaxDynamicSharedMemorySize, DSMEM_BYTES);
    cudaFuncSetAttribute(gemm_mma<3>, cudaFuncAttributeMaxDynamicSharedMemorySize, DSMEM_BYTES);
    cudaFuncSetAttribute(gemm_mma<4>, cudaFuncAttributeMaxDynamicSharedMemorySize, DSMEM_BYTES);
    cudaFuncSetAttribute(attn_mma_kernel, cudaFuncAttributeMaxDynamicSharedMemorySize, AT_SMEM);

    // 1. prep: weight conversion + modulation (single kernel)
    PrepArgs pa;
    pa.src[0] = qkv_s_w;  pa.src[1] = qkv_a_w;  pa.src[2] = attn_in_w;
    pa.src[3] = attn_out_w; pa.src[4] = mw1s;   pa.src[5] = mw2s;
    pa.src[6] = mw1a;     pa.src[7] = mw2a;
    pa.sz = state_z; pa.az = action_z; pa.e = e;
    prep_kernel<<<30720, 256>>>(pa);

    // 2. merged QKV GEMM with fused RoPE+concat -> g_qkvb (bf16)
    dim3 gq(D3 / 128, 64);
    gemm_mma<0><<<gq, 256, DSMEM_BYTES>>>(xsb, xab, wall + O_WQS, wall + O_WQA,
                                          qkv_s_b, qkv_a_b, nullptr, nullptr,
                                          nullptr, nullptr, nullptr);

    // 3. merged head projections (thirds q,k,v) -> fp16 head-major g_hh
    dim3 gh(ND / 128, 192);
    gemm_mma<1><<<gh, 256, DSMEM_BYTES>>>(qkvb, nullptr, wall + O_WAI, nullptr,
                                          attn_in_b, nullptr, hh, nullptr,
                                          nullptr, nullptr, nullptr);

    // 4. attention
    dim3 ga(S2 / 128, NH, NB);
    attn_mma_kernel<<<ga, 256, AT_SMEM>>>();

    // 5. output projection -> bf16
    dim3 go(ND / 128, 64);
    gemm_mma<4><<<go, 256, DSMEM_BYTES>>>(ob, nullptr, wall + O_WAO, nullptr,
                                          attn_out_b, nullptr, yb, nullptr,
                                          nullptr, nullptr, nullptr);

    // 6. merged MLP1 (fast gelu) -> g_h1b (both branches)
    dim3 g1(D4 / 128, 64);
    gemm_mma<2><<<g1, 256, DSMEM_BYTES>>>(yb, nullptr, wall + O_W1S, wall + O_W1A,
                                          mb1s, mb1a, h1b, nullptr,
                                          nullptr, nullptr, nullptr);

    // 7. merged MLP2 (gated residual) -> out
    dim3 g2(ND / 128, 64);
    gemm_mma<3><<<g2, 256, DSMEM_BYTES>>>(h1b, nullptr, wall + O_W2S, wall + O_W2A,
                                          mb2s, mb2a, out, nullptr,
                                          state_z, action_z, e);
}